// round 1
// baseline (speedup 1.0000x reference)
#include <cuda_runtime.h>
#include <math.h>

// ---------------------------------------------------------------------------
// Problem constants
// ---------------------------------------------------------------------------
#define BATCH   16384
#define NHIST   50
#define DIM     128
#define NITEMS  100000
#define NUSERS  100000

// ---------------------------------------------------------------------------
// Scratch (static device globals — no allocation in kernel_launch)
// ---------------------------------------------------------------------------
__device__ float g_Kt [NITEMS * DIM];   // relu(item_table @ gat_wk + bk)
__device__ float g_Vt [NITEMS * DIM];   // relu(item_table @ gat_wv + bv)
__device__ float g_Qg [BATCH * DIM];    // relu(node @ gat_wq + bq)
__device__ float g_Q2 [BATCH * DIM];    // relu(node @ sem_wq + bq)
__device__ float g_K0 [BATCH * DIM];    // relu(node @ sem_wk + bk)
__device__ float g_V0 [BATCH * DIM];    // relu(node @ sem_wv + bv)
__device__ float g_K1 [BATCH * DIM];    // relu(agg  @ sem_wk + bk)
__device__ float g_V1 [BATCH * DIM];    // relu(agg  @ sem_wv + bv)
__device__ float g_Y  [BATCH * DIM];    // gat attention output (pre-wo)
__device__ float g_Agg[BATCH * DIM];    // relu(Y @ gat_wo + bo)
__device__ float g_Y2 [BATCH * DIM];    // sem attention output (pre-wo)

// ---------------------------------------------------------------------------
// GEMM: C[M,128] = relu(A[gidx[m],:128] @ W[128,128] + bias)
// 128x128 CTA tile, BK=8, 256 threads, 8x8 microtile, register prefetch.
// ---------------------------------------------------------------------------
#define BM 128
#define BN 128
#define BK 8
#define TM 8
#define TN 8

__global__ void __launch_bounds__(256, 2)
gemm_bias_relu(const float* __restrict__ A, const int* __restrict__ gidx,
               const float* __restrict__ W, const float* __restrict__ bias,
               float* __restrict__ C, int M)
{
    __shared__ float As[BK][BM];   // transposed: As[k][m]
    __shared__ float Bs[BK][BN];   // Bs[k][n]

    const int tid = threadIdx.x;
    const int tx  = tid & 15;      // 0..15 -> column group
    const int ty  = tid >> 4;      // 0..15 -> row group
    const int rowBase = blockIdx.x * BM;

    // A staging: each thread loads one float4 along K.
    // 128 rows x 8 k-cols / 4 = 256 float4. thread t -> row t/2, kcol (t%2)*4
    const int arow = tid >> 1;
    const int acol = (tid & 1) << 2;
    int grow = rowBase + arow;
    if (grow >= M) grow = M - 1;                 // clamp (row never written)
    const int asrc = gidx ? gidx[grow] : grow;
    const float* aptr = A + (long)asrc * DIM + acol;

    // B staging: 8 k-rows x 128 n / 4 = 256 float4. thread t -> k t/32, n (t%32)*4
    const int bk = tid >> 5;
    const int bn = (tid & 31) << 2;
    const float* bptr = W + bk * DIM + bn;

    float acc[TM][TN];
    #pragma unroll
    for (int i = 0; i < TM; i++)
        #pragma unroll
        for (int j = 0; j < TN; j++)
            acc[i][j] = 0.f;

    float4 aReg = *(const float4*)(aptr);
    float4 bReg = *(const float4*)(bptr);

    #pragma unroll
    for (int kt = 0; kt < DIM / BK; ++kt) {
        As[acol + 0][arow] = aReg.x;
        As[acol + 1][arow] = aReg.y;
        As[acol + 2][arow] = aReg.z;
        As[acol + 3][arow] = aReg.w;
        *(float4*)&Bs[bk][bn] = bReg;
        __syncthreads();

        if (kt + 1 < DIM / BK) {                 // prefetch next stage
            aReg = *(const float4*)(aptr + (kt + 1) * BK);
            bReg = *(const float4*)(bptr + (kt + 1) * BK * DIM);
        }

        #pragma unroll
        for (int kk = 0; kk < BK; ++kk) {
            float af[TM], bf[TN];
            *(float4*)&af[0] = *(const float4*)&As[kk][ty * TM + 0];
            *(float4*)&af[4] = *(const float4*)&As[kk][ty * TM + 4];
            *(float4*)&bf[0] = *(const float4*)&Bs[kk][tx * TN + 0];
            *(float4*)&bf[4] = *(const float4*)&Bs[kk][tx * TN + 4];
            #pragma unroll
            for (int i = 0; i < TM; i++)
                #pragma unroll
                for (int j = 0; j < TN; j++)
                    acc[i][j] = fmaf(af[i], bf[j], acc[i][j]);
        }
        __syncthreads();
    }

    // Epilogue: bias + relu, vectorized stores
    #pragma unroll
    for (int i = 0; i < TM; i++) {
        const int r = rowBase + ty * TM + i;
        if (r < M) {
            #pragma unroll
            for (int j = 0; j < TN; j += 4) {
                const int c = tx * TN + j;
                float4 o;
                o.x = fmaxf(acc[i][j + 0] + bias[c + 0], 0.f);
                o.y = fmaxf(acc[i][j + 1] + bias[c + 1], 0.f);
                o.z = fmaxf(acc[i][j + 2] + bias[c + 2], 0.f);
                o.w = fmaxf(acc[i][j + 3] + bias[c + 3], 0.f);
                *(float4*)(C + (long)r * DIM + c) = o;
            }
        }
    }
}

// ---------------------------------------------------------------------------
// GAT attention: one warp per batch element, 8 warps per CTA.
// scores_h = dot(q, Kt[idx_h]) / sqrt(D) ; softmax over 50 ; y = sum p_h Vt[idx_h]
// ---------------------------------------------------------------------------
__global__ void __launch_bounds__(256)
gat_attn(const float* __restrict__ Q, const int* __restrict__ movies,
         const float* __restrict__ Kt, const float* __restrict__ Vt,
         float* __restrict__ Y)
{
    const int w    = threadIdx.x >> 5;
    const int lane = threadIdx.x & 31;
    const int b    = blockIdx.x * 8 + w;

    __shared__ int   sidx[8][NHIST];
    __shared__ float sp  [8][NHIST];

    // load history item indices (column 0 of [B,H,2])
    if (lane < NHIST)      sidx[w][lane]      = movies[(b * NHIST + lane) * 2];
    if (lane + 32 < NHIST) sidx[w][lane + 32] = movies[(b * NHIST + lane + 32) * 2];
    __syncwarp();

    const float4 q = *(const float4*)(Q + (long)b * DIM + lane * 4);

    // ---- scores (chunks of 10 for MLP) ----
    for (int h0 = 0; h0 < NHIST; h0 += 10) {
        float4 kr[10];
        #pragma unroll
        for (int j = 0; j < 10; j++)
            kr[j] = *(const float4*)(Kt + (long)sidx[w][h0 + j] * DIM + lane * 4);
        float s[10];
        #pragma unroll
        for (int j = 0; j < 10; j++)
            s[j] = q.x * kr[j].x + q.y * kr[j].y + q.z * kr[j].z + q.w * kr[j].w;
        #pragma unroll
        for (int j = 0; j < 10; j++)
            #pragma unroll
            for (int off = 16; off; off >>= 1)
                s[j] += __shfl_xor_sync(0xffffffffu, s[j], off);
        if (lane == 0) {
            #pragma unroll
            for (int j = 0; j < 10; j++) sp[w][h0 + j] = s[j];
        }
    }
    __syncwarp();

    // ---- softmax over 50 ----
    const float scale = 0.08838834764831845f;   // 1/sqrt(128)
    float a0 = (lane < NHIST)      ? sp[w][lane]      * scale : -1e30f;
    float a1 = (lane + 32 < NHIST) ? sp[w][lane + 32] * scale : -1e30f;
    float m = fmaxf(a0, a1);
    #pragma unroll
    for (int off = 16; off; off >>= 1)
        m = fmaxf(m, __shfl_xor_sync(0xffffffffu, m, off));
    float e0 = (lane < NHIST)      ? __expf(a0 - m) : 0.f;
    float e1 = (lane + 32 < NHIST) ? __expf(a1 - m) : 0.f;
    float es = e0 + e1;
    #pragma unroll
    for (int off = 16; off; off >>= 1)
        es += __shfl_xor_sync(0xffffffffu, es, off);
    const float inv = 1.0f / es;
    if (lane < NHIST)      sp[w][lane]      = e0 * inv;
    if (lane + 32 < NHIST) sp[w][lane + 32] = e1 * inv;
    __syncwarp();

    // ---- weighted sum of V ----
    float4 acc = make_float4(0.f, 0.f, 0.f, 0.f);
    for (int h0 = 0; h0 < NHIST; h0 += 10) {
        #pragma unroll
        for (int j = 0; j < 10; j++) {
            const float  p = sp[w][h0 + j];
            const float4 v = *(const float4*)(Vt + (long)sidx[w][h0 + j] * DIM + lane * 4);
            acc.x = fmaf(p, v.x, acc.x);
            acc.y = fmaf(p, v.y, acc.y);
            acc.z = fmaf(p, v.z, acc.z);
            acc.w = fmaf(p, v.w, acc.w);
        }
    }
    *(float4*)(Y + (long)b * DIM + lane * 4) = acc;
}

// ---------------------------------------------------------------------------
// SEM attention over 2 keys (node, agg): one warp per batch element.
// ---------------------------------------------------------------------------
__global__ void __launch_bounds__(256)
sem_attn(const float* __restrict__ Q2, const float* __restrict__ K0,
         const float* __restrict__ K1, const float* __restrict__ V0,
         const float* __restrict__ V1, float* __restrict__ Y2)
{
    const int w    = threadIdx.x >> 5;
    const int lane = threadIdx.x & 31;
    const int b    = blockIdx.x * 8 + w;
    const long off = (long)b * DIM + lane * 4;

    const float4 q  = *(const float4*)(Q2 + off);
    const float4 k0 = *(const float4*)(K0 + off);
    const float4 k1 = *(const float4*)(K1 + off);

    float s0 = q.x * k0.x + q.y * k0.y + q.z * k0.z + q.w * k0.w;
    float s1 = q.x * k1.x + q.y * k1.y + q.z * k1.z + q.w * k1.w;
    #pragma unroll
    for (int o = 16; o; o >>= 1) {
        s0 += __shfl_xor_sync(0xffffffffu, s0, o);
        s1 += __shfl_xor_sync(0xffffffffu, s1, o);
    }
    const float scale = 0.08838834764831845f;
    s0 *= scale; s1 *= scale;
    const float m  = fmaxf(s0, s1);
    const float e0 = __expf(s0 - m);
    const float e1 = __expf(s1 - m);
    const float inv = 1.0f / (e0 + e1);
    const float p0 = e0 * inv, p1 = e1 * inv;

    const float4 v0 = *(const float4*)(V0 + off);
    const float4 v1 = *(const float4*)(V1 + off);
    float4 y;
    y.x = p0 * v0.x + p1 * v1.x;
    y.y = p0 * v0.y + p1 * v1.y;
    y.z = p0 * v0.z + p1 * v1.z;
    y.w = p0 * v0.w + p1 * v1.w;
    *(float4*)(Y2 + off) = y;
}

// ---------------------------------------------------------------------------
// Host launcher
// ---------------------------------------------------------------------------
extern "C" void kernel_launch(void* const* d_in, const int* in_sizes, int n_in,
                              void* d_out, int out_size)
{
    const int*   uids       = (const int*)  d_in[0];
    // d_in[1] qids, d_in[4] query_table: unused by the reference output
    const int*   u_movies   = (const int*)  d_in[2];
    const float* user_table = (const float*)d_in[3];
    const float* item_table = (const float*)d_in[5];
    const float* gat_wq = (const float*)d_in[6],  *gat_bq = (const float*)d_in[7];
    const float* gat_wk = (const float*)d_in[8],  *gat_bk = (const float*)d_in[9];
    const float* gat_wv = (const float*)d_in[10], *gat_bv = (const float*)d_in[11];
    const float* gat_wo = (const float*)d_in[12], *gat_bo = (const float*)d_in[13];
    const float* sem_wq = (const float*)d_in[14], *sem_bq = (const float*)d_in[15];
    const float* sem_wk = (const float*)d_in[16], *sem_bk = (const float*)d_in[17];
    const float* sem_wv = (const float*)d_in[18], *sem_bv = (const float*)d_in[19];
    const float* sem_wo = (const float*)d_in[20], *sem_bo = (const float*)d_in[21];
    float* out = (float*)d_out;

    float *Kt, *Vt, *Qg, *Q2, *K0, *V0, *K1, *V1, *Y, *Agg, *Y2;
    cudaGetSymbolAddress((void**)&Kt,  g_Kt);
    cudaGetSymbolAddress((void**)&Vt,  g_Vt);
    cudaGetSymbolAddress((void**)&Qg,  g_Qg);
    cudaGetSymbolAddress((void**)&Q2,  g_Q2);
    cudaGetSymbolAddress((void**)&K0,  g_K0);
    cudaGetSymbolAddress((void**)&V0,  g_V0);
    cudaGetSymbolAddress((void**)&K1,  g_K1);
    cudaGetSymbolAddress((void**)&V1,  g_V1);
    cudaGetSymbolAddress((void**)&Y,   g_Y);
    cudaGetSymbolAddress((void**)&Agg, g_Agg);
    cudaGetSymbolAddress((void**)&Y2,  g_Y2);

    const int gItems = (NITEMS + BM - 1) / BM;   // 782
    const int gBatch = BATCH / BM;               // 128
    const dim3 blk(256);

    // 1-2: precompute item K/V transforms (8x FLOP reduction vs gathered GEMM)
    gemm_bias_relu<<<gItems, blk>>>(item_table, nullptr, gat_wk, gat_bk, Kt, NITEMS);
    gemm_bias_relu<<<gItems, blk>>>(item_table, nullptr, gat_wv, gat_bv, Vt, NITEMS);

    // 3-6: per-batch node transforms (gathered by uids)
    gemm_bias_relu<<<gBatch, blk>>>(user_table, uids, gat_wq, gat_bq, Qg, BATCH);
    gemm_bias_relu<<<gBatch, blk>>>(user_table, uids, sem_wq, sem_bq, Q2, BATCH);
    gemm_bias_relu<<<gBatch, blk>>>(user_table, uids, sem_wk, sem_bk, K0, BATCH);
    gemm_bias_relu<<<gBatch, blk>>>(user_table, uids, sem_wv, sem_bv, V0, BATCH);

    // 7: GAT attention over 50 gathered history items
    gat_attn<<<BATCH / 8, blk>>>(Qg, u_movies, Kt, Vt, Y);

    // 8: agg = relu(Y @ gat_wo + bo)
    gemm_bias_relu<<<gBatch, blk>>>(Y, nullptr, gat_wo, gat_bo, Agg, BATCH);

    // 9-10: sem K/V of agg
    gemm_bias_relu<<<gBatch, blk>>>(Agg, nullptr, sem_wk, sem_bk, K1, BATCH);
    gemm_bias_relu<<<gBatch, blk>>>(Agg, nullptr, sem_wv, sem_bv, V1, BATCH);

    // 11: sem attention over {node, agg}
    sem_attn<<<BATCH / 8, blk>>>(Q2, K0, K1, V0, V1, Y2);

    // 12: final projection straight into d_out
    gemm_bias_relu<<<gBatch, blk>>>(Y2, nullptr, sem_wo, sem_bo, out, BATCH);
}

// round 2
// speedup vs baseline: 1.4796x; 1.4796x over previous
#include <cuda_runtime.h>
#include <math.h>

// ---------------------------------------------------------------------------
// Problem constants
// ---------------------------------------------------------------------------
#define BATCH   16384
#define NHIST   50
#define DIM     128
#define NITEMS  100000

// ---------------------------------------------------------------------------
// Scratch (static device globals — no allocation in kernel_launch)
// ---------------------------------------------------------------------------
__device__ float g_Kt [NITEMS * DIM];
__device__ float g_Vt [NITEMS * DIM];
__device__ float g_Qg [BATCH * DIM];
__device__ float g_Q2 [BATCH * DIM];
__device__ float g_K0 [BATCH * DIM];
__device__ float g_V0 [BATCH * DIM];
__device__ float g_K1 [BATCH * DIM];
__device__ float g_V1 [BATCH * DIM];
__device__ float g_Y  [BATCH * DIM];
__device__ float g_Agg[BATCH * DIM];
__device__ float g_Y2 [BATCH * DIM];

// ---------------------------------------------------------------------------
// Packed f32x2 helpers (FFMA2 — 2x fp32 rate; ptxas never emits from C++)
// ---------------------------------------------------------------------------
union F4U2 { float4 f; unsigned long long u[2]; };

__device__ __forceinline__ unsigned long long pk2(float lo, float hi) {
    unsigned long long r;
    asm("mov.b64 %0, {%1, %2};" : "=l"(r) : "f"(lo), "f"(hi));
    return r;
}
__device__ __forceinline__ void fma2(unsigned long long& d,
                                     unsigned long long a, unsigned long long b) {
    asm("fma.rn.f32x2 %0, %1, %2, %0;" : "+l"(d) : "l"(a), "l"(b));
}

// ---------------------------------------------------------------------------
// Multi-weight GEMM: C_y[M,128] = relu(A[gidx[m]] @ W_y + b_y), y = blockIdx.y
// BM=64 rows/CTA, BK=16, 256 threads, 4x8 microtile, FFMA2 inner loop.
// ---------------------------------------------------------------------------
#define BM 64
#define BK 16

struct GSet { const float* W; const float* bias; float* C; };

__global__ void __launch_bounds__(256, 2)
gemm_multi(const float* __restrict__ A, const int* __restrict__ gidx,
           GSet s0, GSet s1, GSet s2, GSet s3, int M)
{
    const GSet s = (blockIdx.y == 0) ? s0 : (blockIdx.y == 1) ? s1
                 : (blockIdx.y == 2) ? s2 : s3;

    __shared__ float As[BM][BK];        // As[m][k]  (k contiguous)
    __shared__ float Bs[BK][DIM];       // Bs[k][n]

    const int tid = threadIdx.x;
    const int tx  = tid & 15;           // col group: cols tx*4 and 64+tx*4
    const int ty  = tid >> 4;           // row group: rows ty*4 .. ty*4+3
    const int rowBase = blockIdx.x * BM;

    // A staging: 64 rows x 16 k = 256 float4, one per thread.
    const int arow = tid >> 2;
    const int akc  = (tid & 3) << 2;
    int grow = rowBase + arow;
    if (grow >= M) grow = M - 1;                       // clamp; never stored
    const int  asrc = gidx ? gidx[grow] : grow;
    const float* aptr = A + (long)asrc * DIM + akc;

    // B staging: 16 k-rows x 128 n = 512 float4, two per thread.
    const int bk = tid >> 5;
    const int bn = (tid & 31) << 2;
    const float* bptr = s.W + bk * DIM + bn;

    unsigned long long acc[4][4];       // [row i][pair j]; j 0,1 -> cols tx*4; 2,3 -> 64+tx*4
    #pragma unroll
    for (int i = 0; i < 4; i++)
        #pragma unroll
        for (int j = 0; j < 4; j++) acc[i][j] = 0ull;

    float4 aReg  = *(const float4*)(aptr);
    float4 bReg0 = *(const float4*)(bptr);
    float4 bReg1 = *(const float4*)(bptr + 8 * DIM);

    #pragma unroll
    for (int kt = 0; kt < DIM / BK; ++kt) {
        *(float4*)&As[arow][akc]   = aReg;
        *(float4*)&Bs[bk][bn]      = bReg0;
        *(float4*)&Bs[bk + 8][bn]  = bReg1;
        __syncthreads();

        if (kt + 1 < DIM / BK) {
            aReg  = *(const float4*)(aptr + (kt + 1) * BK);
            bReg0 = *(const float4*)(bptr + (kt + 1) * BK * DIM);
            bReg1 = *(const float4*)(bptr + (kt + 1) * BK * DIM + 8 * DIM);
        }

        #pragma unroll
        for (int kk4 = 0; kk4 < 4; ++kk4) {
            float4 a4[4];
            #pragma unroll
            for (int i = 0; i < 4; i++)
                a4[i] = *(const float4*)&As[ty * 4 + i][kk4 * 4];

            #pragma unroll
            for (int kki = 0; kki < 4; ++kki) {
                const int kk = kk4 * 4 + kki;
                F4U2 b0, b1;
                b0.f = *(const float4*)&Bs[kk][tx * 4];
                b1.f = *(const float4*)&Bs[kk][64 + tx * 4];
                #pragma unroll
                for (int i = 0; i < 4; i++) {
                    const float av = (kki == 0) ? a4[i].x : (kki == 1) ? a4[i].y
                                   : (kki == 2) ? a4[i].z : a4[i].w;
                    const unsigned long long pa = pk2(av, av);
                    fma2(acc[i][0], pa, b0.u[0]);
                    fma2(acc[i][1], pa, b0.u[1]);
                    fma2(acc[i][2], pa, b1.u[0]);
                    fma2(acc[i][3], pa, b1.u[1]);
                }
            }
        }
        __syncthreads();
    }

    // Epilogue: bias + relu
    const float4 biasA = *(const float4*)(s.bias + tx * 4);
    const float4 biasB = *(const float4*)(s.bias + 64 + tx * 4);
    #pragma unroll
    for (int i = 0; i < 4; i++) {
        const int r = rowBase + ty * 4 + i;
        if (r < M) {
            F4U2 oA, oB;
            oA.u[0] = acc[i][0]; oA.u[1] = acc[i][1];
            oB.u[0] = acc[i][2]; oB.u[1] = acc[i][3];
            float4 wa, wb;
            wa.x = fmaxf(oA.f.x + biasA.x, 0.f);
            wa.y = fmaxf(oA.f.y + biasA.y, 0.f);
            wa.z = fmaxf(oA.f.z + biasA.z, 0.f);
            wa.w = fmaxf(oA.f.w + biasA.w, 0.f);
            wb.x = fmaxf(oB.f.x + biasB.x, 0.f);
            wb.y = fmaxf(oB.f.y + biasB.y, 0.f);
            wb.z = fmaxf(oB.f.z + biasB.z, 0.f);
            wb.w = fmaxf(oB.f.w + biasB.w, 0.f);
            *(float4*)(s.C + (long)r * DIM + tx * 4)      = wa;
            *(float4*)(s.C + (long)r * DIM + 64 + tx * 4) = wb;
        }
    }
}

// ---------------------------------------------------------------------------
// GAT attention: one warp per batch element, 8 warps per CTA.
// ---------------------------------------------------------------------------
__global__ void __launch_bounds__(256)
gat_attn(const float* __restrict__ Q, const int* __restrict__ movies,
         const float* __restrict__ Kt, const float* __restrict__ Vt,
         float* __restrict__ Y)
{
    const int w    = threadIdx.x >> 5;
    const int lane = threadIdx.x & 31;
    const int b    = blockIdx.x * 8 + w;

    __shared__ int   sidx[8][NHIST];
    __shared__ float sp  [8][NHIST];

    if (lane < NHIST)      sidx[w][lane]      = movies[(b * NHIST + lane) * 2];
    if (lane + 32 < NHIST) sidx[w][lane + 32] = movies[(b * NHIST + lane + 32) * 2];
    __syncwarp();

    const float4 q = *(const float4*)(Q + (long)b * DIM + lane * 4);

    for (int h0 = 0; h0 < NHIST; h0 += 10) {
        float4 kr[10];
        #pragma unroll
        for (int j = 0; j < 10; j++)
            kr[j] = *(const float4*)(Kt + (long)sidx[w][h0 + j] * DIM + lane * 4);
        float sc[10];
        #pragma unroll
        for (int j = 0; j < 10; j++)
            sc[j] = q.x * kr[j].x + q.y * kr[j].y + q.z * kr[j].z + q.w * kr[j].w;
        #pragma unroll
        for (int j = 0; j < 10; j++)
            #pragma unroll
            for (int off = 16; off; off >>= 1)
                sc[j] += __shfl_xor_sync(0xffffffffu, sc[j], off);
        if (lane == 0) {
            #pragma unroll
            for (int j = 0; j < 10; j++) sp[w][h0 + j] = sc[j];
        }
    }
    __syncwarp();

    const float scale = 0.08838834764831845f;
    float a0 = (lane < NHIST)      ? sp[w][lane]      * scale : -1e30f;
    float a1 = (lane + 32 < NHIST) ? sp[w][lane + 32] * scale : -1e30f;
    float m = fmaxf(a0, a1);
    #pragma unroll
    for (int off = 16; off; off >>= 1)
        m = fmaxf(m, __shfl_xor_sync(0xffffffffu, m, off));
    float e0 = (lane < NHIST)      ? __expf(a0 - m) : 0.f;
    float e1 = (lane + 32 < NHIST) ? __expf(a1 - m) : 0.f;
    float es = e0 + e1;
    #pragma unroll
    for (int off = 16; off; off >>= 1)
        es += __shfl_xor_sync(0xffffffffu, es, off);
    const float inv = 1.0f / es;
    if (lane < NHIST)      sp[w][lane]      = e0 * inv;
    if (lane + 32 < NHIST) sp[w][lane + 32] = e1 * inv;
    __syncwarp();

    float4 acc = make_float4(0.f, 0.f, 0.f, 0.f);
    for (int h0 = 0; h0 < NHIST; h0 += 10) {
        #pragma unroll
        for (int j = 0; j < 10; j++) {
            const float  p = sp[w][h0 + j];
            const float4 v = *(const float4*)(Vt + (long)sidx[w][h0 + j] * DIM + lane * 4);
            acc.x = fmaf(p, v.x, acc.x);
            acc.y = fmaf(p, v.y, acc.y);
            acc.z = fmaf(p, v.z, acc.z);
            acc.w = fmaf(p, v.w, acc.w);
        }
    }
    *(float4*)(Y + (long)b * DIM + lane * 4) = acc;
}

// ---------------------------------------------------------------------------
// SEM attention over 2 keys
// ---------------------------------------------------------------------------
__global__ void __launch_bounds__(256)
sem_attn(const float* __restrict__ Q2, const float* __restrict__ K0,
         const float* __restrict__ K1, const float* __restrict__ V0,
         const float* __restrict__ V1, float* __restrict__ Y2)
{
    const int lane = threadIdx.x & 31;
    const int b    = blockIdx.x * 8 + (threadIdx.x >> 5);
    const long off = (long)b * DIM + lane * 4;

    const float4 q  = *(const float4*)(Q2 + off);
    const float4 k0 = *(const float4*)(K0 + off);
    const float4 k1 = *(const float4*)(K1 + off);

    float s0 = q.x * k0.x + q.y * k0.y + q.z * k0.z + q.w * k0.w;
    float s1 = q.x * k1.x + q.y * k1.y + q.z * k1.z + q.w * k1.w;
    #pragma unroll
    for (int o = 16; o; o >>= 1) {
        s0 += __shfl_xor_sync(0xffffffffu, s0, o);
        s1 += __shfl_xor_sync(0xffffffffu, s1, o);
    }
    const float scale = 0.08838834764831845f;
    s0 *= scale; s1 *= scale;
    const float m  = fmaxf(s0, s1);
    const float e0 = __expf(s0 - m);
    const float e1 = __expf(s1 - m);
    const float inv = 1.0f / (e0 + e1);
    const float p0 = e0 * inv, p1 = e1 * inv;

    const float4 v0 = *(const float4*)(V0 + off);
    const float4 v1 = *(const float4*)(V1 + off);
    float4 y;
    y.x = p0 * v0.x + p1 * v1.x;
    y.y = p0 * v0.y + p1 * v1.y;
    y.z = p0 * v0.z + p1 * v1.z;
    y.w = p0 * v0.w + p1 * v1.w;
    *(float4*)(Y2 + off) = y;
}

// ---------------------------------------------------------------------------
// Host launcher (7 launches)
// ---------------------------------------------------------------------------
extern "C" void kernel_launch(void* const* d_in, const int* in_sizes, int n_in,
                              void* d_out, int out_size)
{
    const int*   uids       = (const int*)  d_in[0];
    const int*   u_movies   = (const int*)  d_in[2];
    const float* user_table = (const float*)d_in[3];
    const float* item_table = (const float*)d_in[5];
    const float* gat_wq = (const float*)d_in[6],  *gat_bq = (const float*)d_in[7];
    const float* gat_wk = (const float*)d_in[8],  *gat_bk = (const float*)d_in[9];
    const float* gat_wv = (const float*)d_in[10], *gat_bv = (const float*)d_in[11];
    const float* gat_wo = (const float*)d_in[12], *gat_bo = (const float*)d_in[13];
    const float* sem_wq = (const float*)d_in[14], *sem_bq = (const float*)d_in[15];
    const float* sem_wk = (const float*)d_in[16], *sem_bk = (const float*)d_in[17];
    const float* sem_wv = (const float*)d_in[18], *sem_bv = (const float*)d_in[19];
    const float* sem_wo = (const float*)d_in[20], *sem_bo = (const float*)d_in[21];
    float* out = (float*)d_out;

    float *Kt, *Vt, *Qg, *Q2, *K0, *V0, *K1, *V1, *Y, *Agg, *Y2;
    cudaGetSymbolAddress((void**)&Kt,  g_Kt);
    cudaGetSymbolAddress((void**)&Vt,  g_Vt);
    cudaGetSymbolAddress((void**)&Qg,  g_Qg);
    cudaGetSymbolAddress((void**)&Q2,  g_Q2);
    cudaGetSymbolAddress((void**)&K0,  g_K0);
    cudaGetSymbolAddress((void**)&V0,  g_V0);
    cudaGetSymbolAddress((void**)&K1,  g_K1);
    cudaGetSymbolAddress((void**)&V1,  g_V1);
    cudaGetSymbolAddress((void**)&Y,   g_Y);
    cudaGetSymbolAddress((void**)&Agg, g_Agg);
    cudaGetSymbolAddress((void**)&Y2,  g_Y2);

    const dim3 blk(256);
    const int gItems = (NITEMS + BM - 1) / BM;   // 1563
    const int gBatch = BATCH / BM;               // 256

    GSet sKt  = { gat_wk, gat_bk, Kt  };
    GSet sVt  = { gat_wv, gat_bv, Vt  };
    GSet sQg  = { gat_wq, gat_bq, Qg  };
    GSet sQ2  = { sem_wq, sem_bq, Q2  };
    GSet sK0  = { sem_wk, sem_bk, K0  };
    GSet sV0  = { sem_wv, sem_bv, V0  };
    GSet sAgg = { gat_wo, gat_bo, Agg };
    GSet sK1  = { sem_wk, sem_bk, K1  };
    GSet sV1  = { sem_wv, sem_bv, V1  };
    GSet sOut = { sem_wo, sem_bo, out };

    // 1: item K/V transforms (fused, grid fills chip: 3126 CTAs)
    gemm_multi<<<dim3(gItems, 2), blk>>>(item_table, nullptr, sKt, sVt, sKt, sKt, NITEMS);

    // 2: node transforms (4 weight sets in one launch: 1024 CTAs)
    gemm_multi<<<dim3(gBatch, 4), blk>>>(user_table, uids, sQg, sQ2, sK0, sV0, BATCH);

    // 3: GAT attention over 50 gathered history items
    gat_attn<<<BATCH / 8, blk>>>(Qg, u_movies, Kt, Vt, Y);

    // 4: agg = relu(Y @ gat_wo + bo)
    gemm_multi<<<dim3(gBatch, 1), blk>>>(Y, nullptr, sAgg, sAgg, sAgg, sAgg, BATCH);

    // 5: sem K/V of agg (fused)
    gemm_multi<<<dim3(gBatch, 2), blk>>>(Agg, nullptr, sK1, sV1, sK1, sK1, BATCH);

    // 6: sem attention over {node, agg}
    sem_attn<<<BATCH / 8, blk>>>(Q2, K0, K1, V0, V1, Y2);

    // 7: final projection into d_out
    gemm_multi<<<dim3(gBatch, 1), blk>>>(Y2, nullptr, sOut, sOut, sOut, sOut, BATCH);
}

// round 4
// speedup vs baseline: 2.0501x; 1.3856x over previous
#include <cuda_runtime.h>
#include <cuda_bf16.h>
#include <math.h>

// ---------------------------------------------------------------------------
// Problem constants
// ---------------------------------------------------------------------------
#define BATCH   16384
#define NHIST   50
#define DIM     128
#define NITEMS  100000

// ---------------------------------------------------------------------------
// Scratch (static device globals)
// ---------------------------------------------------------------------------
__device__ float g_Kt [NITEMS * DIM];
__device__ float g_Vt [NITEMS * DIM];
__device__ float g_Qg [BATCH * DIM];
__device__ float g_Q2 [BATCH * DIM];
__device__ float g_K0 [BATCH * DIM];
__device__ float g_V0 [BATCH * DIM];
__device__ float g_K1 [BATCH * DIM];
__device__ float g_V1 [BATCH * DIM];
__device__ float g_Y  [BATCH * DIM];
__device__ float g_Agg[BATCH * DIM];
__device__ float g_Y2 [BATCH * DIM];
// bf16 weight splits, transposed to [n][k]: slot 2*w = hi, 2*w+1 = lo
// w: 0=gat_wq 1=gat_wk 2=gat_wv 3=gat_wo 4=sem_wq 5=sem_wk 6=sem_wv 7=sem_wo
__device__ unsigned short g_W4[16][DIM * DIM];

// ---------------------------------------------------------------------------
// helpers
// ---------------------------------------------------------------------------
__device__ __forceinline__ unsigned smem_u32(const void* p) {
    unsigned a;
    asm("{ .reg .u64 t; cvta.to.shared.u64 t, %1; cvt.u32.u64 %0, t; }"
        : "=r"(a) : "l"(p));
    return a;
}
__device__ __forceinline__ void ldm4(unsigned& r0, unsigned& r1,
                                     unsigned& r2, unsigned& r3, unsigned addr) {
    asm volatile("ldmatrix.sync.aligned.m8n8.x4.shared.b16 {%0,%1,%2,%3}, [%4];"
                 : "=r"(r0), "=r"(r1), "=r"(r2), "=r"(r3) : "r"(addr));
}
__device__ __forceinline__ void mma16816(float* d, const unsigned* a, const unsigned* b) {
    asm volatile("mma.sync.aligned.m16n8k16.row.col.f32.bf16.bf16.f32 "
                 "{%0,%1,%2,%3}, {%4,%5,%6,%7}, {%8,%9}, {%0,%1,%2,%3};"
                 : "+f"(d[0]), "+f"(d[1]), "+f"(d[2]), "+f"(d[3])
                 : "r"(a[0]), "r"(a[1]), "r"(a[2]), "r"(a[3]),
                   "r"(b[0]), "r"(b[1]));
}
// smem byte offset for (row, 8-bf16 chunk kc): 256B rows, XOR swizzle on chunk
__device__ __forceinline__ unsigned sw_off(int row, int kc) {
    return (unsigned)(row * 256 + ((kc ^ (row & 7)) << 4));
}
// split 8 fp32 -> two uint4 of bf16 (hi, lo = residual)
__device__ __forceinline__ void split8(const float* xs, uint4& H, uint4& L) {
    unsigned hw[4], lw[4];
    #pragma unroll
    for (int j = 0; j < 4; j++) {
        __nv_bfloat16 h0 = __float2bfloat16(xs[2*j]);
        __nv_bfloat16 h1 = __float2bfloat16(xs[2*j+1]);
        __nv_bfloat16 l0 = __float2bfloat16(xs[2*j]   - __bfloat162float(h0));
        __nv_bfloat16 l1 = __float2bfloat16(xs[2*j+1] - __bfloat162float(h1));
        hw[j] = (unsigned)*(unsigned short*)&h0 | ((unsigned)*(unsigned short*)&h1 << 16);
        lw[j] = (unsigned)*(unsigned short*)&l0 | ((unsigned)*(unsigned short*)&l1 << 16);
    }
    H = make_uint4(hw[0], hw[1], hw[2], hw[3]);
    L = make_uint4(lw[0], lw[1], lw[2], lw[3]);
}

// ===========================================================================
// Setup: transpose + bf16-split all 8 weight matrices
// ===========================================================================
__global__ void w_setup(const float* w0, const float* w1, const float* w2,
                        const float* w3, const float* w4, const float* w5,
                        const float* w6, const float* w7)
{
    const int i = blockIdx.x * blockDim.x + threadIdx.x;
    if (i >= DIM * DIM) return;
    const float* ws[8] = {w0, w1, w2, w3, w4, w5, w6, w7};
    const int k = i >> 7, n = i & 127;
    const int dst = n * DIM + k;
    #pragma unroll
    for (int w = 0; w < 8; w++) {
        const float a = ws[w][i];
        __nv_bfloat16 h = __float2bfloat16(a);
        __nv_bfloat16 l = __float2bfloat16(a - __bfloat162float(h));
        g_W4[2*w    ][dst] = *(unsigned short*)&h;
        g_W4[2*w + 1][dst] = *(unsigned short*)&l;
    }
}

// ===========================================================================
// Unified HMMA GEMM: C_y[m,:] = relu(A[gidx[m]] @ W_y + b_y)
// 128x128 CTA tile, 8 warps (4x2), warp tile 32x64, bf16 3-term compensation.
// ===========================================================================
#define SM_AHI  0
#define SM_ALO  32768
#define SM_WHI  65536
#define SM_WLO  98304
#define SM_BIAS 131072
#define HSMEM   131584

struct HSet { int wslot; const float* bias; float* C; };

__global__ void __launch_bounds__(256, 1)
gemm_hmma(const float* __restrict__ A, const int* __restrict__ gidx,
          HSet s0, HSet s1, HSet s2, HSet s3, int M)
{
    const HSet s = (blockIdx.y == 0) ? s0 : (blockIdx.y == 1) ? s1
                 : (blockIdx.y == 2) ? s2 : s3;

    extern __shared__ char sm[];
    const unsigned sb = smem_u32(sm);

    const int tid  = threadIdx.x;
    const int wid  = tid >> 5;
    const int lane = tid & 31;
    const int wm   = wid & 3;            // 0..3  (m direction, 32 rows)
    const int wn   = wid >> 2;           // 0..1  (n direction, 64 cols)
    const int rowBase = blockIdx.x * 128;

    if (tid < 128) ((float*)(sm + SM_BIAS))[tid] = s.bias[tid];

    // --- A staging: gather + fp32 -> bf16 hi/lo split, swizzled ----------
    #pragma unroll
    for (int u = 0; u < 8; u++) {
        const int g  = u * 256 + tid;
        const int r  = g >> 4, kc = g & 15;
        int R = rowBase + r; if (R >= M) R = M - 1;
        const int src = gidx ? gidx[R] : R;
        const float4 x0 = *(const float4*)(A + (long)src * DIM + kc * 8);
        const float4 x1 = *(const float4*)(A + (long)src * DIM + kc * 8 + 4);
        const float xs[8] = {x0.x, x0.y, x0.z, x0.w, x1.x, x1.y, x1.z, x1.w};
        uint4 H, L;
        split8(xs, H, L);
        const unsigned o = sw_off(r, kc);
        *(uint4*)(sm + SM_AHI + o) = H;
        *(uint4*)(sm + SM_ALO + o) = L;
    }

    // --- W staging: pre-split bf16 [n][k] -> swizzled smem ----------------
    {
        const unsigned short* WH = g_W4[2 * s.wslot];
        const unsigned short* WL = g_W4[2 * s.wslot + 1];
        #pragma unroll
        for (int u = 0; u < 8; u++) {
            const int g  = u * 256 + tid;
            const int n  = g >> 4, kc = g & 15;
            const unsigned o = sw_off(n, kc);
            *(uint4*)(sm + SM_WHI + o) = *(const uint4*)(WH + n * DIM + kc * 8);
            *(uint4*)(sm + SM_WLO + o) = *(const uint4*)(WL + n * DIM + kc * 8);
        }
    }
    __syncthreads();

    float acc[2][8][4];
    #pragma unroll
    for (int i = 0; i < 2; i++)
        #pragma unroll
        for (int j = 0; j < 8; j++)
            #pragma unroll
            for (int q = 0; q < 4; q++) acc[i][j][q] = 0.f;

    // --- main loop over K (8 steps of 16) ---------------------------------
    #pragma unroll
    for (int ks = 0; ks < 8; ks++) {
        unsigned aH[2][4], aL[2][4], bH[8][2], bL[8][2];

        // A fragments (2 m-tiles of 16)
        {
            const int r  = wm * 32 + (lane & 15);
            const int kc = ks * 2 + (lane >> 4);
            ldm4(aH[0][0], aH[0][1], aH[0][2], aH[0][3], sb + SM_AHI + sw_off(r,      kc));
            ldm4(aH[1][0], aH[1][1], aH[1][2], aH[1][3], sb + SM_AHI + sw_off(r + 16, kc));
            ldm4(aL[0][0], aL[0][1], aL[0][2], aL[0][3], sb + SM_ALO + sw_off(r,      kc));
            ldm4(aL[1][0], aL[1][1], aL[1][2], aL[1][3], sb + SM_ALO + sw_off(r + 16, kc));
        }
        // B fragments (8 n-tiles of 8; one ldm4 covers 2 n-tiles)
        {
            const int grp  = lane >> 3;                       // 0..3
            const int nloc = (lane & 7) + ((grp >> 1) << 3);  // +8 for grp 2,3
            const int kc   = ks * 2 + (grp & 1);
            #pragma unroll
            for (int j = 0; j < 4; j++) {
                const int n = wn * 64 + j * 16 + nloc;
                ldm4(bH[2*j][0], bH[2*j][1], bH[2*j+1][0], bH[2*j+1][1],
                     sb + SM_WHI + sw_off(n, kc));
                ldm4(bL[2*j][0], bL[2*j][1], bL[2*j+1][0], bL[2*j+1][1],
                     sb + SM_WLO + sw_off(n, kc));
            }
        }
        // 3-term compensated MMA
        #pragma unroll
        for (int mf = 0; mf < 2; mf++)
            #pragma unroll
            for (int nf = 0; nf < 8; nf++) {
                mma16816(acc[mf][nf], aH[mf], bH[nf]);
                mma16816(acc[mf][nf], aH[mf], bL[nf]);
                mma16816(acc[mf][nf], aL[mf], bH[nf]);
            }
    }

    // --- epilogue: bias + relu, direct stores ------------------------------
    const float* sbias = (const float*)(sm + SM_BIAS);
    #pragma unroll
    for (int mf = 0; mf < 2; mf++) {
        const int r0 = rowBase + wm * 32 + mf * 16 + (lane >> 2);
        #pragma unroll
        for (int nf = 0; nf < 8; nf++) {
            const int c  = wn * 64 + nf * 8 + (lane & 3) * 2;
            const float b0 = sbias[c], b1 = sbias[c + 1];
            if (r0 < M) {
                float2 v;
                v.x = fmaxf(acc[mf][nf][0] + b0, 0.f);
                v.y = fmaxf(acc[mf][nf][1] + b1, 0.f);
                *(float2*)(s.C + (long)r0 * DIM + c) = v;
            }
            if (r0 + 8 < M) {
                float2 v;
                v.x = fmaxf(acc[mf][nf][2] + b0, 0.f);
                v.y = fmaxf(acc[mf][nf][3] + b1, 0.f);
                *(float2*)(s.C + (long)(r0 + 8) * DIM + c) = v;
            }
        }
    }
}

// ---------------------------------------------------------------------------
// GAT attention: one warp per batch element, 8 warps per CTA.
// ---------------------------------------------------------------------------
__global__ void __launch_bounds__(256)
gat_attn(const float* __restrict__ Q, const int* __restrict__ movies,
         const float* __restrict__ Kt, const float* __restrict__ Vt,
         float* __restrict__ Y)
{
    const int w    = threadIdx.x >> 5;
    const int lane = threadIdx.x & 31;
    const int b    = blockIdx.x * 8 + w;

    __shared__ int   sidx[8][NHIST];
    __shared__ float sp  [8][NHIST];

    if (lane < NHIST)      sidx[w][lane]      = movies[(b * NHIST + lane) * 2];
    if (lane + 32 < NHIST) sidx[w][lane + 32] = movies[(b * NHIST + lane + 32) * 2];
    __syncwarp();

    const float4 q = *(const float4*)(Q + (long)b * DIM + lane * 4);

    for (int h0 = 0; h0 < NHIST; h0 += 10) {
        float4 kr[10];
        #pragma unroll
        for (int j = 0; j < 10; j++)
            kr[j] = *(const float4*)(Kt + (long)sidx[w][h0 + j] * DIM + lane * 4);
        float sc[10];
        #pragma unroll
        for (int j = 0; j < 10; j++)
            sc[j] = q.x * kr[j].x + q.y * kr[j].y + q.z * kr[j].z + q.w * kr[j].w;
        #pragma unroll
        for (int j = 0; j < 10; j++)
            #pragma unroll
            for (int off = 16; off; off >>= 1)
                sc[j] += __shfl_xor_sync(0xffffffffu, sc[j], off);
        if (lane == 0) {
            #pragma unroll
            for (int j = 0; j < 10; j++) sp[w][h0 + j] = sc[j];
        }
    }
    __syncwarp();

    const float scale = 0.08838834764831845f;
    float a0 = (lane < NHIST)      ? sp[w][lane]      * scale : -1e30f;
    float a1 = (lane + 32 < NHIST) ? sp[w][lane + 32] * scale : -1e30f;
    float m = fmaxf(a0, a1);
    #pragma unroll
    for (int off = 16; off; off >>= 1)
        m = fmaxf(m, __shfl_xor_sync(0xffffffffu, m, off));
    float e0 = (lane < NHIST)      ? __expf(a0 - m) : 0.f;
    float e1 = (lane + 32 < NHIST) ? __expf(a1 - m) : 0.f;
    float es = e0 + e1;
    #pragma unroll
    for (int off = 16; off; off >>= 1)
        es += __shfl_xor_sync(0xffffffffu, es, off);
    const float inv = 1.0f / es;
    if (lane < NHIST)      sp[w][lane]      = e0 * inv;
    if (lane + 32 < NHIST) sp[w][lane + 32] = e1 * inv;
    __syncwarp();

    float4 acc = make_float4(0.f, 0.f, 0.f, 0.f);
    for (int h0 = 0; h0 < NHIST; h0 += 10) {
        #pragma unroll
        for (int j = 0; j < 10; j++) {
            const float  p = sp[w][h0 + j];
            const float4 v = *(const float4*)(Vt + (long)sidx[w][h0 + j] * DIM + lane * 4);
            acc.x = fmaf(p, v.x, acc.x);
            acc.y = fmaf(p, v.y, acc.y);
            acc.z = fmaf(p, v.z, acc.z);
            acc.w = fmaf(p, v.w, acc.w);
        }
    }
    *(float4*)(Y + (long)b * DIM + lane * 4) = acc;
}

// ---------------------------------------------------------------------------
// SEM attention over 2 keys
// ---------------------------------------------------------------------------
__global__ void __launch_bounds__(256)
sem_attn(const float* __restrict__ Q2, const float* __restrict__ K0,
         const float* __restrict__ K1, const float* __restrict__ V0,
         const float* __restrict__ V1, float* __restrict__ Y2)
{
    const int lane = threadIdx.x & 31;
    const int b    = blockIdx.x * 8 + (threadIdx.x >> 5);
    const long off = (long)b * DIM + lane * 4;

    const float4 q  = *(const float4*)(Q2 + off);
    const float4 k0 = *(const float4*)(K0 + off);
    const float4 k1 = *(const float4*)(K1 + off);

    float s0 = q.x * k0.x + q.y * k0.y + q.z * k0.z + q.w * k0.w;
    float s1 = q.x * k1.x + q.y * k1.y + q.z * k1.z + q.w * k1.w;
    #pragma unroll
    for (int o = 16; o; o >>= 1) {
        s0 += __shfl_xor_sync(0xffffffffu, s0, o);
        s1 += __shfl_xor_sync(0xffffffffu, s1, o);
    }
    const float scale = 0.08838834764831845f;
    s0 *= scale; s1 *= scale;
    const float m  = fmaxf(s0, s1);
    const float e0 = __expf(s0 - m);
    const float e1 = __expf(s1 - m);
    const float inv = 1.0f / (e0 + e1);
    const float p0 = e0 * inv, p1 = e1 * inv;

    const float4 v0 = *(const float4*)(V0 + off);
    const float4 v1 = *(const float4*)(V1 + off);
    float4 y;
    y.x = p0 * v0.x + p1 * v1.x;
    y.y = p0 * v0.y + p1 * v1.y;
    y.z = p0 * v0.z + p1 * v1.z;
    y.w = p0 * v0.w + p1 * v1.w;
    *(float4*)(Y2 + off) = y;
}

// ---------------------------------------------------------------------------
// Host launcher
// ---------------------------------------------------------------------------
extern "C" void kernel_launch(void* const* d_in, const int* in_sizes, int n_in,
                              void* d_out, int out_size)
{
    const int*   uids       = (const int*)  d_in[0];
    const int*   u_movies   = (const int*)  d_in[2];
    const float* user_table = (const float*)d_in[3];
    const float* item_table = (const float*)d_in[5];
    const float* gat_wq = (const float*)d_in[6],  *gat_bq = (const float*)d_in[7];
    const float* gat_wk = (const float*)d_in[8],  *gat_bk = (const float*)d_in[9];
    const float* gat_wv = (const float*)d_in[10], *gat_bv = (const float*)d_in[11];
    const float* gat_wo = (const float*)d_in[12], *gat_bo = (const float*)d_in[13];
    const float* sem_wq = (const float*)d_in[14], *sem_bq = (const float*)d_in[15];
    const float* sem_wk = (const float*)d_in[16], *sem_bk = (const float*)d_in[17];
    const float* sem_wv = (const float*)d_in[18], *sem_bv = (const float*)d_in[19];
    const float* sem_wo = (const float*)d_in[20], *sem_bo = (const float*)d_in[21];
    float* out = (float*)d_out;

    float *Kt, *Vt, *Qg, *Q2, *K0, *V0, *K1, *V1, *Y, *Agg, *Y2;
    cudaGetSymbolAddress((void**)&Kt,  g_Kt);
    cudaGetSymbolAddress((void**)&Vt,  g_Vt);
    cudaGetSymbolAddress((void**)&Qg,  g_Qg);
    cudaGetSymbolAddress((void**)&Q2,  g_Q2);
    cudaGetSymbolAddress((void**)&K0,  g_K0);
    cudaGetSymbolAddress((void**)&V0,  g_V0);
    cudaGetSymbolAddress((void**)&K1,  g_K1);
    cudaGetSymbolAddress((void**)&V1,  g_V1);
    cudaGetSymbolAddress((void**)&Y,   g_Y);
    cudaGetSymbolAddress((void**)&Agg, g_Agg);
    cudaGetSymbolAddress((void**)&Y2,  g_Y2);

    static bool attr_done = false;
    if (!attr_done) {
        cudaFuncSetAttribute(gemm_hmma, cudaFuncAttributeMaxDynamicSharedMemorySize, HSMEM);
        attr_done = true;
    }

    const dim3 blk(256);
    const int gItems = (NITEMS + 127) / 128;     // 782
    const int gBatch = BATCH / 128;              // 128

    // weight slots: 0=gat_wq 1=gat_wk 2=gat_wv 3=gat_wo 4=sem_wq 5=sem_wk 6=sem_wv 7=sem_wo
    HSet sKt  = { 1, gat_bk, Kt  };
    HSet sVt  = { 2, gat_bv, Vt  };
    HSet sQg  = { 0, gat_bq, Qg  };
    HSet sQ2  = { 4, sem_bq, Q2  };
    HSet sK0  = { 5, sem_bk, K0  };
    HSet sV0  = { 6, sem_bv, V0  };
    HSet sAgg = { 3, gat_bo, Agg };
    HSet sK1  = { 5, sem_bk, K1  };
    HSet sV1  = { 6, sem_bv, V1  };
    HSet sOut = { 7, sem_bo, out };

    // 0: weight transpose + bf16 split (8 matrices)
    w_setup<<<64, 256>>>(gat_wq, gat_wk, gat_wv, gat_wo,
                         sem_wq, sem_wk, sem_wv, sem_wo);

    // 1: item K/V transforms (tensor cores, 1564 CTAs)
    gemm_hmma<<<dim3(gItems, 2), blk, HSMEM>>>(item_table, nullptr,
                                               sKt, sVt, sKt, sKt, NITEMS);

    // 2: node transforms (gathered, 4 weight sets)
    gemm_hmma<<<dim3(gBatch, 4), blk, HSMEM>>>(user_table, uids,
                                               sQg, sQ2, sK0, sV0, BATCH);

    // 3: GAT attention over 50 gathered history items
    gat_attn<<<BATCH / 8, blk>>>(Qg, u_movies, Kt, Vt, Y);

    // 4: agg = relu(Y @ gat_wo + bo)
    gemm_hmma<<<dim3(gBatch, 1), blk, HSMEM>>>(Y, nullptr,
                                               sAgg, sAgg, sAgg, sAgg, BATCH);

    // 5: sem K/V of agg
    gemm_hmma<<<dim3(gBatch, 2), blk, HSMEM>>>(Agg, nullptr,
                                               sK1, sV1, sK1, sK1, BATCH);

    // 6: sem attention over {node, agg}
    sem_attn<<<BATCH / 8, blk>>>(Q2, K0, K1, V0, V1, Y2);

    // 7: final projection into d_out
    gemm_hmma<<<dim3(gBatch, 1), blk, HSMEM>>>(Y2, nullptr,
                                               sOut, sOut, sOut, sOut, BATCH);
}

// round 5
// speedup vs baseline: 2.2863x; 1.1152x over previous
#include <cuda_runtime.h>
#include <cuda_bf16.h>
#include <math.h>

// ---------------------------------------------------------------------------
// Problem constants
// ---------------------------------------------------------------------------
#define BATCH   16384
#define NHIST   50
#define DIM     128
#define NITEMS  100000

// ---------------------------------------------------------------------------
// Scratch (static device globals)
// ---------------------------------------------------------------------------
__device__ __nv_bfloat16 g_KV[NITEMS * 256];   // per item: 128 bf16 K | 128 bf16 V
__device__ float g_Qg [BATCH * DIM];
__device__ float g_Q2 [BATCH * DIM];
__device__ float g_K0 [BATCH * DIM];
__device__ float g_V0 [BATCH * DIM];
__device__ float g_K1 [BATCH * DIM];
__device__ float g_V1 [BATCH * DIM];
__device__ float g_Y  [BATCH * DIM];
__device__ float g_Agg[BATCH * DIM];
__device__ float g_Y2 [BATCH * DIM];
// bf16 weight splits, transposed to [n][k]: slot 2*w = hi, 2*w+1 = lo
// w: 0=gat_wq 1=gat_wk 2=gat_wv 3=gat_wo 4=sem_wq 5=sem_wk 6=sem_wv 7=sem_wo
__device__ unsigned short g_W4[16][DIM * DIM];

// ---------------------------------------------------------------------------
// helpers
// ---------------------------------------------------------------------------
__device__ __forceinline__ unsigned smem_u32(const void* p) {
    unsigned a;
    asm("{ .reg .u64 t; cvta.to.shared.u64 t, %1; cvt.u32.u64 %0, t; }"
        : "=r"(a) : "l"(p));
    return a;
}
__device__ __forceinline__ void ldm4(unsigned& r0, unsigned& r1,
                                     unsigned& r2, unsigned& r3, unsigned addr) {
    asm volatile("ldmatrix.sync.aligned.m8n8.x4.shared.b16 {%0,%1,%2,%3}, [%4];"
                 : "=r"(r0), "=r"(r1), "=r"(r2), "=r"(r3) : "r"(addr));
}
__device__ __forceinline__ void mma16816(float* d, const unsigned* a, const unsigned* b) {
    asm volatile("mma.sync.aligned.m16n8k16.row.col.f32.bf16.bf16.f32 "
                 "{%0,%1,%2,%3}, {%4,%5,%6,%7}, {%8,%9}, {%0,%1,%2,%3};"
                 : "+f"(d[0]), "+f"(d[1]), "+f"(d[2]), "+f"(d[3])
                 : "r"(a[0]), "r"(a[1]), "r"(a[2]), "r"(a[3]),
                   "r"(b[0]), "r"(b[1]));
}
// smem byte offset for (row, 8-bf16 chunk kc): 256B rows, XOR swizzle on chunk
__device__ __forceinline__ unsigned sw_off(int row, int kc) {
    return (unsigned)(row * 256 + ((kc ^ (row & 7)) << 4));
}
// split 8 fp32 -> two uint4 of bf16 (hi, lo = residual)
__device__ __forceinline__ void split8(const float* xs, uint4& H, uint4& L) {
    unsigned hw[4], lw[4];
    #pragma unroll
    for (int j = 0; j < 4; j++) {
        __nv_bfloat16 h0 = __float2bfloat16(xs[2*j]);
        __nv_bfloat16 h1 = __float2bfloat16(xs[2*j+1]);
        __nv_bfloat16 l0 = __float2bfloat16(xs[2*j]   - __bfloat162float(h0));
        __nv_bfloat16 l1 = __float2bfloat16(xs[2*j+1] - __bfloat162float(h1));
        hw[j] = (unsigned)*(unsigned short*)&h0 | ((unsigned)*(unsigned short*)&h1 << 16);
        lw[j] = (unsigned)*(unsigned short*)&l0 | ((unsigned)*(unsigned short*)&l1 << 16);
    }
    H = make_uint4(hw[0], hw[1], hw[2], hw[3]);
    L = make_uint4(lw[0], lw[1], lw[2], lw[3]);
}

// ===========================================================================
// Setup: transpose + bf16-split all 8 weight matrices
// ===========================================================================
__global__ void w_setup(const float* w0, const float* w1, const float* w2,
                        const float* w3, const float* w4, const float* w5,
                        const float* w6, const float* w7)
{
    const int i = blockIdx.x * blockDim.x + threadIdx.x;
    if (i >= DIM * DIM) return;
    const float* ws[8] = {w0, w1, w2, w3, w4, w5, w6, w7};
    const int k = i >> 7, n = i & 127;
    const int dst = n * DIM + k;
    #pragma unroll
    for (int w = 0; w < 8; w++) {
        const float a = ws[w][i];
        __nv_bfloat16 h = __float2bfloat16(a);
        __nv_bfloat16 l = __float2bfloat16(a - __bfloat162float(h));
        g_W4[2*w    ][dst] = *(unsigned short*)&h;
        g_W4[2*w + 1][dst] = *(unsigned short*)&l;
    }
}

// ===========================================================================
// Unified HMMA GEMM: C_y[m,:] = relu(A[gidx[m]] @ W_y + b_y)
// 128x128 CTA tile, 8 warps (4x2), warp tile 32x64, bf16 3-term compensation.
// Output either fp32 (C) or bf16 strided (Cb, cstride) for the KV table.
// ===========================================================================
#define SM_AHI  0
#define SM_ALO  32768
#define SM_WHI  65536
#define SM_WLO  98304
#define SM_BIAS 131072
#define HSMEM   131584

struct HSet { int wslot; const float* bias; float* C; __nv_bfloat16* Cb; int cstride; };

__global__ void __launch_bounds__(256, 1)
gemm_hmma(const float* __restrict__ A, const int* __restrict__ gidx,
          HSet s0, HSet s1, HSet s2, HSet s3, int M)
{
    const HSet s = (blockIdx.y == 0) ? s0 : (blockIdx.y == 1) ? s1
                 : (blockIdx.y == 2) ? s2 : s3;

    extern __shared__ char sm[];
    const unsigned sb = smem_u32(sm);

    const int tid  = threadIdx.x;
    const int wid  = tid >> 5;
    const int lane = tid & 31;
    const int wm   = wid & 3;
    const int wn   = wid >> 2;
    const int rowBase = blockIdx.x * 128;

    if (tid < 128) ((float*)(sm + SM_BIAS))[tid] = s.bias[tid];

    // --- A staging: gather + fp32 -> bf16 hi/lo split, swizzled ----------
    #pragma unroll
    for (int u = 0; u < 8; u++) {
        const int g  = u * 256 + tid;
        const int r  = g >> 4, kc = g & 15;
        int R = rowBase + r; if (R >= M) R = M - 1;
        const int src = gidx ? gidx[R] : R;
        const float4 x0 = *(const float4*)(A + (long)src * DIM + kc * 8);
        const float4 x1 = *(const float4*)(A + (long)src * DIM + kc * 8 + 4);
        const float xs[8] = {x0.x, x0.y, x0.z, x0.w, x1.x, x1.y, x1.z, x1.w};
        uint4 H, L;
        split8(xs, H, L);
        const unsigned o = sw_off(r, kc);
        *(uint4*)(sm + SM_AHI + o) = H;
        *(uint4*)(sm + SM_ALO + o) = L;
    }

    // --- W staging ---------------------------------------------------------
    {
        const unsigned short* WH = g_W4[2 * s.wslot];
        const unsigned short* WL = g_W4[2 * s.wslot + 1];
        #pragma unroll
        for (int u = 0; u < 8; u++) {
            const int g  = u * 256 + tid;
            const int n  = g >> 4, kc = g & 15;
            const unsigned o = sw_off(n, kc);
            *(uint4*)(sm + SM_WHI + o) = *(const uint4*)(WH + n * DIM + kc * 8);
            *(uint4*)(sm + SM_WLO + o) = *(const uint4*)(WL + n * DIM + kc * 8);
        }
    }
    __syncthreads();

    float acc[2][8][4];
    #pragma unroll
    for (int i = 0; i < 2; i++)
        #pragma unroll
        for (int j = 0; j < 8; j++)
            #pragma unroll
            for (int q = 0; q < 4; q++) acc[i][j][q] = 0.f;

    // --- main loop over K (8 steps of 16) ---------------------------------
    #pragma unroll
    for (int ks = 0; ks < 8; ks++) {
        unsigned aH[2][4], aL[2][4], bH[8][2], bL[8][2];
        {
            const int r  = wm * 32 + (lane & 15);
            const int kc = ks * 2 + (lane >> 4);
            ldm4(aH[0][0], aH[0][1], aH[0][2], aH[0][3], sb + SM_AHI + sw_off(r,      kc));
            ldm4(aH[1][0], aH[1][1], aH[1][2], aH[1][3], sb + SM_AHI + sw_off(r + 16, kc));
            ldm4(aL[0][0], aL[0][1], aL[0][2], aL[0][3], sb + SM_ALO + sw_off(r,      kc));
            ldm4(aL[1][0], aL[1][1], aL[1][2], aL[1][3], sb + SM_ALO + sw_off(r + 16, kc));
        }
        {
            const int grp  = lane >> 3;
            const int nloc = (lane & 7) + ((grp >> 1) << 3);
            const int kc   = ks * 2 + (grp & 1);
            #pragma unroll
            for (int j = 0; j < 4; j++) {
                const int n = wn * 64 + j * 16 + nloc;
                ldm4(bH[2*j][0], bH[2*j][1], bH[2*j+1][0], bH[2*j+1][1],
                     sb + SM_WHI + sw_off(n, kc));
                ldm4(bL[2*j][0], bL[2*j][1], bL[2*j+1][0], bL[2*j+1][1],
                     sb + SM_WLO + sw_off(n, kc));
            }
        }
        #pragma unroll
        for (int mf = 0; mf < 2; mf++)
            #pragma unroll
            for (int nf = 0; nf < 8; nf++) {
                mma16816(acc[mf][nf], aH[mf], bH[nf]);
                mma16816(acc[mf][nf], aH[mf], bL[nf]);
                mma16816(acc[mf][nf], aL[mf], bH[nf]);
            }
    }

    // --- epilogue: bias + relu ---------------------------------------------
    const float* sbias = (const float*)(sm + SM_BIAS);
    #pragma unroll
    for (int mf = 0; mf < 2; mf++) {
        const int r0 = rowBase + wm * 32 + mf * 16 + (lane >> 2);
        #pragma unroll
        for (int nf = 0; nf < 8; nf++) {
            const int c  = wn * 64 + nf * 8 + (lane & 3) * 2;
            const float b0 = sbias[c], b1 = sbias[c + 1];
            const float v00 = fmaxf(acc[mf][nf][0] + b0, 0.f);
            const float v01 = fmaxf(acc[mf][nf][1] + b1, 0.f);
            const float v10 = fmaxf(acc[mf][nf][2] + b0, 0.f);
            const float v11 = fmaxf(acc[mf][nf][3] + b1, 0.f);
            if (s.Cb) {
                if (r0 < M) {
                    __nv_bfloat162 v;
                    v.x = __float2bfloat16(v00); v.y = __float2bfloat16(v01);
                    *(__nv_bfloat162*)(s.Cb + (long)r0 * s.cstride + c) = v;
                }
                if (r0 + 8 < M) {
                    __nv_bfloat162 v;
                    v.x = __float2bfloat16(v10); v.y = __float2bfloat16(v11);
                    *(__nv_bfloat162*)(s.Cb + (long)(r0 + 8) * s.cstride + c) = v;
                }
            } else {
                if (r0 < M)
                    *(float2*)(s.C + (long)r0 * DIM + c) = make_float2(v00, v01);
                if (r0 + 8 < M)
                    *(float2*)(s.C + (long)(r0 + 8) * DIM + c) = make_float2(v10, v11);
            }
        }
    }
}

// ---------------------------------------------------------------------------
// GAT attention on the interleaved bf16 KV table: one warp per batch element.
// ---------------------------------------------------------------------------
__global__ void __launch_bounds__(256)
gat_attn(const float* __restrict__ Q, const int* __restrict__ movies,
         const __nv_bfloat16* __restrict__ KV, float* __restrict__ Y)
{
    const int w    = threadIdx.x >> 5;
    const int lane = threadIdx.x & 31;
    const int b    = blockIdx.x * 8 + w;

    __shared__ int   sidx[8][NHIST];
    __shared__ float sp  [8][NHIST];

    if (lane < NHIST)      sidx[w][lane]      = movies[(b * NHIST + lane) * 2];
    if (lane + 32 < NHIST) sidx[w][lane + 32] = movies[(b * NHIST + lane + 32) * 2];
    __syncwarp();

    const float4 q = *(const float4*)(Q + (long)b * DIM + lane * 4);

    // ---- scores (K half of KV rows; 256 B per row, one uint2 per lane) ----
    for (int h0 = 0; h0 < NHIST; h0 += 10) {
        float sc[10];
        #pragma unroll
        for (int j = 0; j < 10; j++) {
            const uint2 u = *(const uint2*)(KV + (long)sidx[w][h0 + j] * 256 + lane * 4);
            const float2 f0 = __bfloat1622float2(*(const __nv_bfloat162*)&u.x);
            const float2 f1 = __bfloat1622float2(*(const __nv_bfloat162*)&u.y);
            sc[j] = q.x * f0.x + q.y * f0.y + q.z * f1.x + q.w * f1.y;
        }
        #pragma unroll
        for (int j = 0; j < 10; j++)
            #pragma unroll
            for (int off = 16; off; off >>= 1)
                sc[j] += __shfl_xor_sync(0xffffffffu, sc[j], off);
        if (lane == 0) {
            #pragma unroll
            for (int j = 0; j < 10; j++) sp[w][h0 + j] = sc[j];
        }
    }
    __syncwarp();

    // ---- softmax over 50 ----
    const float scale = 0.08838834764831845f;
    float a0 = (lane < NHIST)      ? sp[w][lane]      * scale : -1e30f;
    float a1 = (lane + 32 < NHIST) ? sp[w][lane + 32] * scale : -1e30f;
    float m = fmaxf(a0, a1);
    #pragma unroll
    for (int off = 16; off; off >>= 1)
        m = fmaxf(m, __shfl_xor_sync(0xffffffffu, m, off));
    float e0 = (lane < NHIST)      ? __expf(a0 - m) : 0.f;
    float e1 = (lane + 32 < NHIST) ? __expf(a1 - m) : 0.f;
    float es = e0 + e1;
    #pragma unroll
    for (int off = 16; off; off >>= 1)
        es += __shfl_xor_sync(0xffffffffu, es, off);
    const float inv = 1.0f / es;
    if (lane < NHIST)      sp[w][lane]      = e0 * inv;
    if (lane + 32 < NHIST) sp[w][lane + 32] = e1 * inv;
    __syncwarp();

    // ---- weighted sum over V half of KV rows ----
    float4 acc = make_float4(0.f, 0.f, 0.f, 0.f);
    for (int h0 = 0; h0 < NHIST; h0 += 10) {
        #pragma unroll
        for (int j = 0; j < 10; j++) {
            const float  p = sp[w][h0 + j];
            const uint2 u = *(const uint2*)(KV + (long)sidx[w][h0 + j] * 256 + 128 + lane * 4);
            const float2 f0 = __bfloat1622float2(*(const __nv_bfloat162*)&u.x);
            const float2 f1 = __bfloat1622float2(*(const __nv_bfloat162*)&u.y);
            acc.x = fmaf(p, f0.x, acc.x);
            acc.y = fmaf(p, f0.y, acc.y);
            acc.z = fmaf(p, f1.x, acc.z);
            acc.w = fmaf(p, f1.y, acc.w);
        }
    }
    *(float4*)(Y + (long)b * DIM + lane * 4) = acc;
}

// ---------------------------------------------------------------------------
// SEM attention over 2 keys
// ---------------------------------------------------------------------------
__global__ void __launch_bounds__(256)
sem_attn(const float* __restrict__ Q2, const float* __restrict__ K0,
         const float* __restrict__ K1, const float* __restrict__ V0,
         const float* __restrict__ V1, float* __restrict__ Y2)
{
    const int lane = threadIdx.x & 31;
    const int b    = blockIdx.x * 8 + (threadIdx.x >> 5);
    const long off = (long)b * DIM + lane * 4;

    const float4 q  = *(const float4*)(Q2 + off);
    const float4 k0 = *(const float4*)(K0 + off);
    const float4 k1 = *(const float4*)(K1 + off);

    float s0 = q.x * k0.x + q.y * k0.y + q.z * k0.z + q.w * k0.w;
    float s1 = q.x * k1.x + q.y * k1.y + q.z * k1.z + q.w * k1.w;
    #pragma unroll
    for (int o = 16; o; o >>= 1) {
        s0 += __shfl_xor_sync(0xffffffffu, s0, o);
        s1 += __shfl_xor_sync(0xffffffffu, s1, o);
    }
    const float scale = 0.08838834764831845f;
    s0 *= scale; s1 *= scale;
    const float m  = fmaxf(s0, s1);
    const float e0 = __expf(s0 - m);
    const float e1 = __expf(s1 - m);
    const float inv = 1.0f / (e0 + e1);
    const float p0 = e0 * inv, p1 = e1 * inv;

    const float4 v0 = *(const float4*)(V0 + off);
    const float4 v1 = *(const float4*)(V1 + off);
    float4 y;
    y.x = p0 * v0.x + p1 * v1.x;
    y.y = p0 * v0.y + p1 * v1.y;
    y.z = p0 * v0.z + p1 * v1.z;
    y.w = p0 * v0.w + p1 * v1.w;
    *(float4*)(Y2 + off) = y;
}

// ---------------------------------------------------------------------------
// Host launcher
// ---------------------------------------------------------------------------
extern "C" void kernel_launch(void* const* d_in, const int* in_sizes, int n_in,
                              void* d_out, int out_size)
{
    const int*   uids       = (const int*)  d_in[0];
    const int*   u_movies   = (const int*)  d_in[2];
    const float* user_table = (const float*)d_in[3];
    const float* item_table = (const float*)d_in[5];
    const float* gat_wq = (const float*)d_in[6],  *gat_bq = (const float*)d_in[7];
    const float* gat_wk = (const float*)d_in[8],  *gat_bk = (const float*)d_in[9];
    const float* gat_wv = (const float*)d_in[10], *gat_bv = (const float*)d_in[11];
    const float* gat_wo = (const float*)d_in[12], *gat_bo = (const float*)d_in[13];
    const float* sem_wq = (const float*)d_in[14], *sem_bq = (const float*)d_in[15];
    const float* sem_wk = (const float*)d_in[16], *sem_bk = (const float*)d_in[17];
    const float* sem_wv = (const float*)d_in[18], *sem_bv = (const float*)d_in[19];
    const float* sem_wo = (const float*)d_in[20], *sem_bo = (const float*)d_in[21];
    float* out = (float*)d_out;

    __nv_bfloat16* KV;
    float *Qg, *Q2, *K0, *V0, *K1, *V1, *Y, *Agg, *Y2;
    cudaGetSymbolAddress((void**)&KV,  g_KV);
    cudaGetSymbolAddress((void**)&Qg,  g_Qg);
    cudaGetSymbolAddress((void**)&Q2,  g_Q2);
    cudaGetSymbolAddress((void**)&K0,  g_K0);
    cudaGetSymbolAddress((void**)&V0,  g_V0);
    cudaGetSymbolAddress((void**)&K1,  g_K1);
    cudaGetSymbolAddress((void**)&V1,  g_V1);
    cudaGetSymbolAddress((void**)&Y,   g_Y);
    cudaGetSymbolAddress((void**)&Agg, g_Agg);
    cudaGetSymbolAddress((void**)&Y2,  g_Y2);

    static bool attr_done = false;
    if (!attr_done) {
        cudaFuncSetAttribute(gemm_hmma, cudaFuncAttributeMaxDynamicSharedMemorySize, HSMEM);
        attr_done = true;
    }

    const dim3 blk(256);
    const int gItems = (NITEMS + 127) / 128;     // 782
    const int gBatch = BATCH / 128;              // 128

    HSet sKt  = { 1, gat_bk, nullptr, KV,       256 };   // K half of KV rows
    HSet sVt  = { 2, gat_bv, nullptr, KV + 128, 256 };   // V half of KV rows
    HSet sQg  = { 0, gat_bq, Qg,  nullptr, 0 };
    HSet sQ2  = { 4, sem_bq, Q2,  nullptr, 0 };
    HSet sK0  = { 5, sem_bk, K0,  nullptr, 0 };
    HSet sV0  = { 6, sem_bv, V0,  nullptr, 0 };
    HSet sAgg = { 3, gat_bo, Agg, nullptr, 0 };
    HSet sK1  = { 5, sem_bk, K1,  nullptr, 0 };
    HSet sV1  = { 6, sem_bv, V1,  nullptr, 0 };
    HSet sOut = { 7, sem_bo, out, nullptr, 0 };

    // 0: weight transpose + bf16 split (8 matrices)
    w_setup<<<64, 256>>>(gat_wq, gat_wk, gat_wv, gat_wo,
                         sem_wq, sem_wk, sem_wv, sem_wo);

    // 1: item K/V transforms -> interleaved bf16 KV table
    gemm_hmma<<<dim3(gItems, 2), blk, HSMEM>>>(item_table, nullptr,
                                               sKt, sVt, sKt, sKt, NITEMS);

    // 2: node transforms (gathered, 4 weight sets)
    gemm_hmma<<<dim3(gBatch, 4), blk, HSMEM>>>(user_table, uids,
                                               sQg, sQ2, sK0, sV0, BATCH);

    // 3: GAT attention over 50 gathered history items (bf16 KV)
    gat_attn<<<BATCH / 8, blk>>>(Qg, u_movies, KV, Y);

    // 4: agg = relu(Y @ gat_wo + bo)
    gemm_hmma<<<dim3(gBatch, 1), blk, HSMEM>>>(Y, nullptr,
                                               sAgg, sAgg, sAgg, sAgg, BATCH);

    // 5: sem K/V of agg
    gemm_hmma<<<dim3(gBatch, 2), blk, HSMEM>>>(Agg, nullptr,
                                               sK1, sV1, sK1, sK1, BATCH);

    // 6: sem attention over {node, agg}
    sem_attn<<<BATCH / 8, blk>>>(Q2, K0, K1, V0, V1, Y2);

    // 7: final projection into d_out
    gemm_hmma<<<dim3(gBatch, 1), blk, HSMEM>>>(Y2, nullptr,
                                               sOut, sOut, sOut, sOut, BATCH);
}

// round 7
// speedup vs baseline: 2.8618x; 1.2517x over previous
#include <cuda_runtime.h>
#include <cuda_bf16.h>
#include <math.h>

// ---------------------------------------------------------------------------
// Problem constants
// ---------------------------------------------------------------------------
#define BATCH   16384
#define NHIST   50
#define DIM     128
#define NITEMS  100000

// ---------------------------------------------------------------------------
// Scratch (static device globals)
// ---------------------------------------------------------------------------
__device__ __nv_bfloat16 g_KV[NITEMS * 256];   // per item: 128 bf16 K | 128 bf16 V
__device__ float g_Qg [BATCH * DIM];
__device__ float g_Q2 [BATCH * DIM];
__device__ float g_K0 [BATCH * DIM];
__device__ float g_V0 [BATCH * DIM];
__device__ float g_K1 [BATCH * DIM];
__device__ float g_V1 [BATCH * DIM];
__device__ float g_Y  [BATCH * DIM];
__device__ float g_Agg[BATCH * DIM];
__device__ float g_Y2 [BATCH * DIM];
// bf16 weight splits, transposed to [n][k]: slot 2*w = hi, 2*w+1 = lo
__device__ unsigned short g_W4[16][DIM * DIM];

// ---------------------------------------------------------------------------
// helpers
// ---------------------------------------------------------------------------
__device__ __forceinline__ unsigned smem_u32(const void* p) {
    unsigned a;
    asm("{ .reg .u64 t; cvta.to.shared.u64 t, %1; cvt.u32.u64 %0, t; }"
        : "=r"(a) : "l"(p));
    return a;
}
__device__ __forceinline__ void ldm4(unsigned& r0, unsigned& r1,
                                     unsigned& r2, unsigned& r3, unsigned addr) {
    asm volatile("ldmatrix.sync.aligned.m8n8.x4.shared.b16 {%0,%1,%2,%3}, [%4];"
                 : "=r"(r0), "=r"(r1), "=r"(r2), "=r"(r3) : "r"(addr));
}
__device__ __forceinline__ void mma16816(float* d, const unsigned* a, const unsigned* b) {
    asm volatile("mma.sync.aligned.m16n8k16.row.col.f32.bf16.bf16.f32 "
                 "{%0,%1,%2,%3}, {%4,%5,%6,%7}, {%8,%9}, {%0,%1,%2,%3};"
                 : "+f"(d[0]), "+f"(d[1]), "+f"(d[2]), "+f"(d[3])
                 : "r"(a[0]), "r"(a[1]), "r"(a[2]), "r"(a[3]),
                   "r"(b[0]), "r"(b[1]));
}
// smem byte offset for (row, 8-bf16 chunk kc): 256B rows, XOR swizzle on chunk
__device__ __forceinline__ unsigned sw_off(int row, int kc) {
    return (unsigned)(row * 256 + ((kc ^ (row & 7)) << 4));
}
// split 8 fp32 -> two uint4 of bf16 (hi, lo = residual)
__device__ __forceinline__ void split8(const float* xs, uint4& H, uint4& L) {
    unsigned hw[4], lw[4];
    #pragma unroll
    for (int j = 0; j < 4; j++) {
        __nv_bfloat16 h0 = __float2bfloat16(xs[2*j]);
        __nv_bfloat16 h1 = __float2bfloat16(xs[2*j+1]);
        __nv_bfloat16 l0 = __float2bfloat16(xs[2*j]   - __bfloat162float(h0));
        __nv_bfloat16 l1 = __float2bfloat16(xs[2*j+1] - __bfloat162float(h1));
        hw[j] = (unsigned)*(unsigned short*)&h0 | ((unsigned)*(unsigned short*)&h1 << 16);
        lw[j] = (unsigned)*(unsigned short*)&l0 | ((unsigned)*(unsigned short*)&l1 << 16);
    }
    H = make_uint4(hw[0], hw[1], hw[2], hw[3]);
    L = make_uint4(lw[0], lw[1], lw[2], lw[3]);
}
__device__ __forceinline__ uint4 pack8hi(const float* xs) {
    unsigned hw[4];
    #pragma unroll
    for (int j = 0; j < 4; j++) {
        __nv_bfloat16 h0 = __float2bfloat16(xs[2*j]);
        __nv_bfloat16 h1 = __float2bfloat16(xs[2*j+1]);
        hw[j] = (unsigned)*(unsigned short*)&h0 | ((unsigned)*(unsigned short*)&h1 << 16);
    }
    return make_uint4(hw[0], hw[1], hw[2], hw[3]);
}
// bf16x2 unpack via shift/mask
__device__ __forceinline__ float bflo(unsigned u) { return __uint_as_float(u << 16); }
__device__ __forceinline__ float bfhi(unsigned u) { return __uint_as_float(u & 0xffff0000u); }

// ===========================================================================
// Setup: transpose + bf16-split all 8 weight matrices
// ===========================================================================
__global__ void w_setup(const float* w0, const float* w1, const float* w2,
                        const float* w3, const float* w4, const float* w5,
                        const float* w6, const float* w7)
{
    const int i = blockIdx.x * blockDim.x + threadIdx.x;
    if (i >= DIM * DIM) return;
    const float* ws[8] = {w0, w1, w2, w3, w4, w5, w6, w7};
    const int k = i >> 7, n = i & 127;
    const int dst = n * DIM + k;
    #pragma unroll
    for (int w = 0; w < 8; w++) {
        const float a = ws[w][i];
        __nv_bfloat16 h = __float2bfloat16(a);
        __nv_bfloat16 l = __float2bfloat16(a - __bfloat162float(h));
        g_W4[2*w    ][dst] = *(unsigned short*)&h;
        g_W4[2*w + 1][dst] = *(unsigned short*)&l;
    }
}

// ===========================================================================
// Unified HMMA GEMM, templated on compensation terms.
// THREE=true : D = Ah*Wh + Ah*Wl + Al*Wh (fp32-accurate; outputs stay fp32)
// THREE=false: D = Ah*Wh + Ah*Wl        (for outputs re-rounded to bf16)
// 128x128 CTA tile, 8 warps (4x2), warp tile 32x64.
// ===========================================================================
struct HSet { int wslot; const float* bias; float* C; __nv_bfloat16* Cb; int cstride; };

template<bool THREE>
__global__ void __launch_bounds__(256)
gemm_hmma(const float* __restrict__ A, const int* __restrict__ gidx,
          HSet s0, HSet s1, HSet s2, HSet s3, int M)
{
    // smem layout (bytes):
    //   A-hi: 0..32K | [A-lo: 32K..64K only if THREE] | W-hi | W-lo | bias
    constexpr unsigned SM_AHI  = 0;
    constexpr unsigned SM_ALO  = 32768;                       // only if THREE
    constexpr unsigned SM_WHI  = THREE ? 65536 : 32768;
    constexpr unsigned SM_WLO  = SM_WHI + 32768;
    constexpr unsigned SM_BIAS = SM_WLO + 32768;

    const HSet s = (blockIdx.y == 0) ? s0 : (blockIdx.y == 1) ? s1
                 : (blockIdx.y == 2) ? s2 : s3;

    extern __shared__ char sm[];
    const unsigned sb = smem_u32(sm);

    const int tid  = threadIdx.x;
    const int wid  = tid >> 5;
    const int lane = tid & 31;
    const int wm   = wid & 3;
    const int wn   = wid >> 2;
    const int rowBase = blockIdx.x * 128;

    if (tid < 128) ((float*)(sm + SM_BIAS))[tid] = s.bias[tid];

    // --- A staging: gather + bf16 split, swizzled ---------------------------
    #pragma unroll
    for (int u = 0; u < 8; u++) {
        const int g  = u * 256 + tid;
        const int r  = g >> 4, kc = g & 15;
        int R = rowBase + r; if (R >= M) R = M - 1;
        const int src = gidx ? gidx[R] : R;
        const float4 x0 = *(const float4*)(A + (long)src * DIM + kc * 8);
        const float4 x1 = *(const float4*)(A + (long)src * DIM + kc * 8 + 4);
        const float xs[8] = {x0.x, x0.y, x0.z, x0.w, x1.x, x1.y, x1.z, x1.w};
        const unsigned o = sw_off(r, kc);
        if (THREE) {
            uint4 H, L;
            split8(xs, H, L);
            *(uint4*)(sm + SM_AHI + o) = H;
            *(uint4*)(sm + SM_ALO + o) = L;
        } else {
            *(uint4*)(sm + SM_AHI + o) = pack8hi(xs);
        }
    }

    // --- W staging ---------------------------------------------------------
    {
        const unsigned short* WH = g_W4[2 * s.wslot];
        const unsigned short* WL = g_W4[2 * s.wslot + 1];
        #pragma unroll
        for (int u = 0; u < 8; u++) {
            const int g  = u * 256 + tid;
            const int n  = g >> 4, kc = g & 15;
            const unsigned o = sw_off(n, kc);
            *(uint4*)(sm + SM_WHI + o) = *(const uint4*)(WH + n * DIM + kc * 8);
            *(uint4*)(sm + SM_WLO + o) = *(const uint4*)(WL + n * DIM + kc * 8);
        }
    }
    __syncthreads();

    float acc[2][8][4];
    #pragma unroll
    for (int i = 0; i < 2; i++)
        #pragma unroll
        for (int j = 0; j < 8; j++)
            #pragma unroll
            for (int q = 0; q < 4; q++) acc[i][j][q] = 0.f;

    // --- main loop over K (8 steps of 16) -----------------------------------
    #pragma unroll
    for (int ks = 0; ks < 8; ks++) {
        unsigned aH[2][4], aL[2][4], bH[8][2], bL[8][2];
        {
            const int r  = wm * 32 + (lane & 15);
            const int kc = ks * 2 + (lane >> 4);
            ldm4(aH[0][0], aH[0][1], aH[0][2], aH[0][3], sb + SM_AHI + sw_off(r,      kc));
            ldm4(aH[1][0], aH[1][1], aH[1][2], aH[1][3], sb + SM_AHI + sw_off(r + 16, kc));
            if (THREE) {
                ldm4(aL[0][0], aL[0][1], aL[0][2], aL[0][3], sb + SM_ALO + sw_off(r,      kc));
                ldm4(aL[1][0], aL[1][1], aL[1][2], aL[1][3], sb + SM_ALO + sw_off(r + 16, kc));
            }
        }
        {
            const int grp  = lane >> 3;
            const int nloc = (lane & 7) + ((grp >> 1) << 3);
            const int kc   = ks * 2 + (grp & 1);
            #pragma unroll
            for (int j = 0; j < 4; j++) {
                const int n = wn * 64 + j * 16 + nloc;
                ldm4(bH[2*j][0], bH[2*j][1], bH[2*j+1][0], bH[2*j+1][1],
                     sb + SM_WHI + sw_off(n, kc));
                ldm4(bL[2*j][0], bL[2*j][1], bL[2*j+1][0], bL[2*j+1][1],
                     sb + SM_WLO + sw_off(n, kc));
            }
        }
        #pragma unroll
        for (int mf = 0; mf < 2; mf++)
            #pragma unroll
            for (int nf = 0; nf < 8; nf++) {
                mma16816(acc[mf][nf], aH[mf], bH[nf]);
                mma16816(acc[mf][nf], aH[mf], bL[nf]);
                if (THREE) mma16816(acc[mf][nf], aL[mf], bH[nf]);
            }
    }

    // --- epilogue: bias + relu ------------------------------------------------
    const float* sbias = (const float*)(sm + SM_BIAS);
    #pragma unroll
    for (int mf = 0; mf < 2; mf++) {
        const int r0 = rowBase + wm * 32 + mf * 16 + (lane >> 2);
        #pragma unroll
        for (int nf = 0; nf < 8; nf++) {
            const int c  = wn * 64 + nf * 8 + (lane & 3) * 2;
            const float b0 = sbias[c], b1 = sbias[c + 1];
            const float v00 = fmaxf(acc[mf][nf][0] + b0, 0.f);
            const float v01 = fmaxf(acc[mf][nf][1] + b1, 0.f);
            const float v10 = fmaxf(acc[mf][nf][2] + b0, 0.f);
            const float v11 = fmaxf(acc[mf][nf][3] + b1, 0.f);
            if (s.Cb) {
                if (r0 < M) {
                    __nv_bfloat162 v;
                    v.x = __float2bfloat16(v00); v.y = __float2bfloat16(v01);
                    *(__nv_bfloat162*)(s.Cb + (long)r0 * s.cstride + c) = v;
                }
                if (r0 + 8 < M) {
                    __nv_bfloat162 v;
                    v.x = __float2bfloat16(v10); v.y = __float2bfloat16(v11);
                    *(__nv_bfloat162*)(s.Cb + (long)(r0 + 8) * s.cstride + c) = v;
                }
            } else {
                if (r0 < M)
                    *(float2*)(s.C + (long)r0 * DIM + c) = make_float2(v00, v01);
                if (r0 + 8 < M)
                    *(float2*)(s.C + (long)(r0 + 8) * DIM + c) = make_float2(v10, v11);
            }
        }
    }
}

#define HSMEM3 (65536 + 65536 + 512)   // 131584: A-hi,A-lo,W-hi,W-lo,bias
#define HSMEM2 (32768 + 65536 + 512)   //  98816: A-hi,W-hi,W-lo,bias

// ---------------------------------------------------------------------------
// GAT attention v2: one warp per batch element; paired-item 16B loads.
// ---------------------------------------------------------------------------
__global__ void __launch_bounds__(256)
gat_attn(const float* __restrict__ Q, const int* __restrict__ movies,
         const __nv_bfloat16* __restrict__ KV, float* __restrict__ Y)
{
    const int w    = threadIdx.x >> 5;
    const int lane = threadIdx.x & 31;
    const int half = lane >> 4;
    const int cl   = lane & 15;
    const int b    = blockIdx.x * 8 + w;

    __shared__ int   sidx[8][NHIST];
    __shared__ float sp  [8][NHIST];

    if (lane < NHIST)      sidx[w][lane]      = movies[(b * NHIST + lane) * 2];
    if (lane + 32 < NHIST) sidx[w][lane + 32] = movies[(b * NHIST + lane + 32) * 2];
    __syncwarp();

    const float4 qa = *(const float4*)(Q + (long)b * DIM + cl * 8);
    const float4 qb = *(const float4*)(Q + (long)b * DIM + cl * 8 + 4);

    // ---- scores: 25 pairs, unrolled by 5 ----------------------------------
    #pragma unroll
    for (int t0 = 0; t0 < 25; t0 += 5) {
        uint4 kr[5];
        #pragma unroll
        for (int j = 0; j < 5; j++)
            kr[j] = *(const uint4*)(KV + (long)sidx[w][2*(t0+j) + half] * 256 + cl * 8);
        float sc[5];
        #pragma unroll
        for (int j = 0; j < 5; j++) {
            float s;
            s  = qa.x * bflo(kr[j].x) + qa.y * bfhi(kr[j].x);
            s += qa.z * bflo(kr[j].y) + qa.w * bfhi(kr[j].y);
            s += qb.x * bflo(kr[j].z) + qb.y * bfhi(kr[j].z);
            s += qb.z * bflo(kr[j].w) + qb.w * bfhi(kr[j].w);
            sc[j] = s;
        }
        #pragma unroll
        for (int j = 0; j < 5; j++)
            #pragma unroll
            for (int off = 8; off; off >>= 1)
                sc[j] += __shfl_xor_sync(0xffffffffu, sc[j], off);
        if (cl == 0) {
            #pragma unroll
            for (int j = 0; j < 5; j++) sp[w][2*(t0+j) + half] = sc[j];
        }
    }
    __syncwarp();

    // ---- softmax over 50 ----
    const float scale = 0.08838834764831845f;
    float a0 = (lane < NHIST)      ? sp[w][lane]      * scale : -1e30f;
    float a1 = (lane + 32 < NHIST) ? sp[w][lane + 32] * scale : -1e30f;
    float m = fmaxf(a0, a1);
    #pragma unroll
    for (int off = 16; off; off >>= 1)
        m = fmaxf(m, __shfl_xor_sync(0xffffffffu, m, off));
    float e0 = (lane < NHIST)      ? __expf(a0 - m) : 0.f;
    float e1 = (lane + 32 < NHIST) ? __expf(a1 - m) : 0.f;
    float es = e0 + e1;
    #pragma unroll
    for (int off = 16; off; off >>= 1)
        es += __shfl_xor_sync(0xffffffffu, es, off);
    const float inv = 1.0f / es;
    if (lane < NHIST)      sp[w][lane]      = e0 * inv;
    if (lane + 32 < NHIST) sp[w][lane + 32] = e1 * inv;
    __syncwarp();

    // ---- weighted V sum ----------------------------------------------------
    float acc[8];
    #pragma unroll
    for (int i = 0; i < 8; i++) acc[i] = 0.f;

    #pragma unroll
    for (int t0 = 0; t0 < 25; t0 += 5) {
        uint4 vr[5];
        float pj[5];
        #pragma unroll
        for (int j = 0; j < 5; j++) {
            vr[j] = *(const uint4*)(KV + (long)sidx[w][2*(t0+j) + half] * 256 + 128 + cl * 8);
            pj[j] = sp[w][2*(t0+j) + half];
        }
        #pragma unroll
        for (int j = 0; j < 5; j++) {
            acc[0] = fmaf(pj[j], bflo(vr[j].x), acc[0]);
            acc[1] = fmaf(pj[j], bfhi(vr[j].x), acc[1]);
            acc[2] = fmaf(pj[j], bflo(vr[j].y), acc[2]);
            acc[3] = fmaf(pj[j], bfhi(vr[j].y), acc[3]);
            acc[4] = fmaf(pj[j], bflo(vr[j].z), acc[4]);
            acc[5] = fmaf(pj[j], bfhi(vr[j].z), acc[5]);
            acc[6] = fmaf(pj[j], bflo(vr[j].w), acc[6]);
            acc[7] = fmaf(pj[j], bfhi(vr[j].w), acc[7]);
        }
    }
    #pragma unroll
    for (int i = 0; i < 8; i++)
        acc[i] += __shfl_xor_sync(0xffffffffu, acc[i], 16);

    if (half == 0) {
        *(float4*)(Y + (long)b * DIM + cl * 8)     = make_float4(acc[0], acc[1], acc[2], acc[3]);
        *(float4*)(Y + (long)b * DIM + cl * 8 + 4) = make_float4(acc[4], acc[5], acc[6], acc[7]);
    }
}

// ---------------------------------------------------------------------------
// SEM attention over 2 keys
// ---------------------------------------------------------------------------
__global__ void __launch_bounds__(256)
sem_attn(const float* __restrict__ Q2, const float* __restrict__ K0,
         const float* __restrict__ K1, const float* __restrict__ V0,
         const float* __restrict__ V1, float* __restrict__ Y2)
{
    const int lane = threadIdx.x & 31;
    const int b    = blockIdx.x * 8 + (threadIdx.x >> 5);
    const long off = (long)b * DIM + lane * 4;

    const float4 q  = *(const float4*)(Q2 + off);
    const float4 k0 = *(const float4*)(K0 + off);
    const float4 k1 = *(const float4*)(K1 + off);

    float s0 = q.x * k0.x + q.y * k0.y + q.z * k0.z + q.w * k0.w;
    float s1 = q.x * k1.x + q.y * k1.y + q.z * k1.z + q.w * k1.w;
    #pragma unroll
    for (int o = 16; o; o >>= 1) {
        s0 += __shfl_xor_sync(0xffffffffu, s0, o);
        s1 += __shfl_xor_sync(0xffffffffu, s1, o);
    }
    const float scale = 0.08838834764831845f;
    s0 *= scale; s1 *= scale;
    const float m  = fmaxf(s0, s1);
    const float e0 = __expf(s0 - m);
    const float e1 = __expf(s1 - m);
    const float inv = 1.0f / (e0 + e1);
    const float p0 = e0 * inv, p1 = e1 * inv;

    const float4 v0 = *(const float4*)(V0 + off);
    const float4 v1 = *(const float4*)(V1 + off);
    float4 y;
    y.x = p0 * v0.x + p1 * v1.x;
    y.y = p0 * v0.y + p1 * v1.y;
    y.z = p0 * v0.z + p1 * v1.z;
    y.w = p0 * v0.w + p1 * v1.w;
    *(float4*)(Y2 + off) = y;
}

// ---------------------------------------------------------------------------
// Host launcher
// ---------------------------------------------------------------------------
extern "C" void kernel_launch(void* const* d_in, const int* in_sizes, int n_in,
                              void* d_out, int out_size)
{
    const int*   uids       = (const int*)  d_in[0];
    const int*   u_movies   = (const int*)  d_in[2];
    const float* user_table = (const float*)d_in[3];
    const float* item_table = (const float*)d_in[5];
    const float* gat_wq = (const float*)d_in[6],  *gat_bq = (const float*)d_in[7];
    const float* gat_wk = (const float*)d_in[8],  *gat_bk = (const float*)d_in[9];
    const float* gat_wv = (const float*)d_in[10], *gat_bv = (const float*)d_in[11];
    const float* gat_wo = (const float*)d_in[12], *gat_bo = (const float*)d_in[13];
    const float* sem_wq = (const float*)d_in[14], *sem_bq = (const float*)d_in[15];
    const float* sem_wk = (const float*)d_in[16], *sem_bk = (const float*)d_in[17];
    const float* sem_wv = (const float*)d_in[18], *sem_bv = (const float*)d_in[19];
    const float* sem_wo = (const float*)d_in[20], *sem_bo = (const float*)d_in[21];
    float* out = (float*)d_out;

    __nv_bfloat16* KV;
    float *Qg, *Q2, *K0, *V0, *K1, *V1, *Y, *Agg, *Y2;
    cudaGetSymbolAddress((void**)&KV,  g_KV);
    cudaGetSymbolAddress((void**)&Qg,  g_Qg);
    cudaGetSymbolAddress((void**)&Q2,  g_Q2);
    cudaGetSymbolAddress((void**)&K0,  g_K0);
    cudaGetSymbolAddress((void**)&V0,  g_V0);
    cudaGetSymbolAddress((void**)&K1,  g_K1);
    cudaGetSymbolAddress((void**)&V1,  g_V1);
    cudaGetSymbolAddress((void**)&Y,   g_Y);
    cudaGetSymbolAddress((void**)&Agg, g_Agg);
    cudaGetSymbolAddress((void**)&Y2,  g_Y2);

    static bool attr_done = false;
    if (!attr_done) {
        cudaFuncSetAttribute(gemm_hmma<true>,  cudaFuncAttributeMaxDynamicSharedMemorySize, HSMEM3);
        cudaFuncSetAttribute(gemm_hmma<false>, cudaFuncAttributeMaxDynamicSharedMemorySize, HSMEM2);
        attr_done = true;
    }

    const dim3 blk(256);
    const int gItems = (NITEMS + 127) / 128;     // 782
    const int gBatch = BATCH / 128;              // 128

    HSet sKt  = { 1, gat_bk, nullptr, KV,       256 };
    HSet sVt  = { 2, gat_bv, nullptr, KV + 128, 256 };
    HSet sQg  = { 0, gat_bq, Qg,  nullptr, 0 };
    HSet sQ2  = { 4, sem_bq, Q2,  nullptr, 0 };
    HSet sK0  = { 5, sem_bk, K0,  nullptr, 0 };
    HSet sV0  = { 6, sem_bv, V0,  nullptr, 0 };
    HSet sAgg = { 3, gat_bo, Agg, nullptr, 0 };
    HSet sK1  = { 5, sem_bk, K1,  nullptr, 0 };
    HSet sV1  = { 6, sem_bv, V1,  nullptr, 0 };
    HSet sOut = { 7, sem_bo, out, nullptr, 0 };

    // 0: weight transpose + bf16 split
    w_setup<<<64, 256>>>(gat_wq, gat_wk, gat_wv, gat_wo,
                         sem_wq, sem_wk, sem_wv, sem_wo);

    // 1: item K/V -> bf16 KV table. 2-term is safe here ONLY because the
    //    output is immediately re-rounded to bf16 (error ~ half an output ulp).
    gemm_hmma<false><<<dim3(gItems, 2), blk, HSMEM2>>>(item_table, nullptr,
                                                       sKt, sVt, sKt, sKt, NITEMS);

    // 2: node transforms (fp32 outputs -> full 3-term)
    gemm_hmma<true><<<dim3(gBatch, 4), blk, HSMEM3>>>(user_table, uids,
                                                      sQg, sQ2, sK0, sV0, BATCH);

    // 3: GAT attention over 50 gathered history items
    gat_attn<<<BATCH / 8, blk>>>(Qg, u_movies, KV, Y);

    // 4: agg = relu(Y @ gat_wo + bo)
    gemm_hmma<true><<<dim3(gBatch, 1), blk, HSMEM3>>>(Y, nullptr,
                                                      sAgg, sAgg, sAgg, sAgg, BATCH);

    // 5: sem K/V of agg
    gemm_hmma<true><<<dim3(gBatch, 2), blk, HSMEM3>>>(Agg, nullptr,
                                                      sK1, sV1, sK1, sK1, BATCH);

    // 6: sem attention over {node, agg}
    sem_attn<<<BATCH / 8, blk>>>(Q2, K0, K1, V0, V1, Y2);

    // 7: final projection into d_out
    gemm_hmma<true><<<dim3(gBatch, 1), blk, HSMEM3>>>(Y2, nullptr,
                                                      sOut, sOut, sOut, sOut, BATCH);
}

// round 8
// speedup vs baseline: 3.2470x; 1.1346x over previous
#include <cuda_runtime.h>
#include <cuda_bf16.h>
#include <cuda_fp16.h>
#include <math.h>

// ---------------------------------------------------------------------------
// Problem constants
// ---------------------------------------------------------------------------
#define BATCH   16384
#define NHIST   50
#define DIM     128
#define NITEMS  100000

// ---------------------------------------------------------------------------
// Scratch (static device globals)
// ---------------------------------------------------------------------------
__device__ __nv_bfloat16 g_KV[NITEMS * 256];   // per item: 128 bf16 K | 128 bf16 V
__device__ float g_Qg [BATCH * DIM];
__device__ float g_Q2 [BATCH * DIM];
__device__ float g_K0 [BATCH * DIM];
__device__ float g_V0 [BATCH * DIM];
__device__ float g_K1 [BATCH * DIM];
__device__ float g_V1 [BATCH * DIM];
__device__ float g_Y  [BATCH * DIM];
// bf16 weight splits, transposed to [n][k]: slot 2*w = hi, 2*w+1 = lo
// w: 0=gat_wq 1=gat_wk 2=gat_wv 3=gat_wo 4=sem_wq 5=sem_wk 6=sem_wv 7=sem_wo
__device__ unsigned short g_W4[16][DIM * DIM];
// fp16 transposed weights for the item GEMM: 0=gat_wk, 1=gat_wv
__device__ unsigned short g_Wh[2][DIM * DIM];

// ---------------------------------------------------------------------------
// helpers
// ---------------------------------------------------------------------------
__device__ __forceinline__ unsigned smem_u32(const void* p) {
    unsigned a;
    asm("{ .reg .u64 t; cvta.to.shared.u64 t, %1; cvt.u32.u64 %0, t; }"
        : "=r"(a) : "l"(p));
    return a;
}
__device__ __forceinline__ void ldm4(unsigned& r0, unsigned& r1,
                                     unsigned& r2, unsigned& r3, unsigned addr) {
    asm volatile("ldmatrix.sync.aligned.m8n8.x4.shared.b16 {%0,%1,%2,%3}, [%4];"
                 : "=r"(r0), "=r"(r1), "=r"(r2), "=r"(r3) : "r"(addr));
}
__device__ __forceinline__ void mma_bf16(float* d, const unsigned* a, const unsigned* b) {
    asm volatile("mma.sync.aligned.m16n8k16.row.col.f32.bf16.bf16.f32 "
                 "{%0,%1,%2,%3}, {%4,%5,%6,%7}, {%8,%9}, {%0,%1,%2,%3};"
                 : "+f"(d[0]), "+f"(d[1]), "+f"(d[2]), "+f"(d[3])
                 : "r"(a[0]), "r"(a[1]), "r"(a[2]), "r"(a[3]),
                   "r"(b[0]), "r"(b[1]));
}
__device__ __forceinline__ void mma_f16(float* d, const unsigned* a, const unsigned* b) {
    asm volatile("mma.sync.aligned.m16n8k16.row.col.f32.f16.f16.f32 "
                 "{%0,%1,%2,%3}, {%4,%5,%6,%7}, {%8,%9}, {%0,%1,%2,%3};"
                 : "+f"(d[0]), "+f"(d[1]), "+f"(d[2]), "+f"(d[3])
                 : "r"(a[0]), "r"(a[1]), "r"(a[2]), "r"(a[3]),
                   "r"(b[0]), "r"(b[1]));
}
// smem byte offset for (row, 8-elem 16B chunk kc): 256B rows, XOR swizzle
__device__ __forceinline__ unsigned sw_off(int row, int kc) {
    return (unsigned)(row * 256 + ((kc ^ (row & 7)) << 4));
}
// split 8 fp32 -> two uint4 of bf16 (hi, lo = residual)
__device__ __forceinline__ void split8(const float* xs, uint4& H, uint4& L) {
    unsigned hw[4], lw[4];
    #pragma unroll
    for (int j = 0; j < 4; j++) {
        __nv_bfloat16 h0 = __float2bfloat16(xs[2*j]);
        __nv_bfloat16 h1 = __float2bfloat16(xs[2*j+1]);
        __nv_bfloat16 l0 = __float2bfloat16(xs[2*j]   - __bfloat162float(h0));
        __nv_bfloat16 l1 = __float2bfloat16(xs[2*j+1] - __bfloat162float(h1));
        hw[j] = (unsigned)*(unsigned short*)&h0 | ((unsigned)*(unsigned short*)&h1 << 16);
        lw[j] = (unsigned)*(unsigned short*)&l0 | ((unsigned)*(unsigned short*)&l1 << 16);
    }
    H = make_uint4(hw[0], hw[1], hw[2], hw[3]);
    L = make_uint4(lw[0], lw[1], lw[2], lw[3]);
}
// 8 fp32 -> uint4 of fp16
__device__ __forceinline__ uint4 pack8f16(const float* xs) {
    unsigned hw[4];
    #pragma unroll
    for (int j = 0; j < 4; j++) {
        const unsigned short a = __half_as_ushort(__float2half_rn(xs[2*j]));
        const unsigned short b = __half_as_ushort(__float2half_rn(xs[2*j+1]));
        hw[j] = (unsigned)a | ((unsigned)b << 16);
    }
    return make_uint4(hw[0], hw[1], hw[2], hw[3]);
}
__device__ __forceinline__ unsigned pack_bf2(float a, float b) {
    __nv_bfloat16 x = __float2bfloat16(a), y = __float2bfloat16(b);
    return (unsigned)*(unsigned short*)&x | ((unsigned)*(unsigned short*)&y << 16);
}
// bf16x2 unpack via shift/mask
__device__ __forceinline__ float bflo(unsigned u) { return __uint_as_float(u << 16); }
__device__ __forceinline__ float bfhi(unsigned u) { return __uint_as_float(u & 0xffff0000u); }

// ===========================================================================
// Setup: transpose + split all weight matrices (bf16 hi/lo; fp16 for wk/wv)
// ===========================================================================
__global__ void w_setup(const float* w0, const float* w1, const float* w2,
                        const float* w3, const float* w4, const float* w5,
                        const float* w6, const float* w7)
{
    const int i = blockIdx.x * blockDim.x + threadIdx.x;
    if (i >= DIM * DIM) return;
    const float* ws[8] = {w0, w1, w2, w3, w4, w5, w6, w7};
    const int k = i >> 7, n = i & 127;
    const int dst = n * DIM + k;
    #pragma unroll
    for (int w = 0; w < 8; w++) {
        const float a = ws[w][i];
        __nv_bfloat16 h = __float2bfloat16(a);
        __nv_bfloat16 l = __float2bfloat16(a - __bfloat162float(h));
        g_W4[2*w    ][dst] = *(unsigned short*)&h;
        g_W4[2*w + 1][dst] = *(unsigned short*)&l;
    }
    g_Wh[0][dst] = __half_as_ushort(__float2half_rn(w1[i]));   // gat_wk
    g_Wh[1][dst] = __half_as_ushort(__float2half_rn(w2[i]));   // gat_wv
}

// ===========================================================================
// Shared GEMM building blocks (3-term bf16): A-hi/A-lo/W-hi/W-lo in smem.
// Warp layout: 8 warps (4x2), warp tile 32x64, CTA tile 128x128.
// ===========================================================================
__device__ __forceinline__ void mma3_loop(
    unsigned sb, unsigned oAhi, unsigned oAlo, unsigned oWhi, unsigned oWlo,
    int wm, int wn, int lane, float acc[2][8][4])
{
    #pragma unroll
    for (int i = 0; i < 2; i++)
        #pragma unroll
        for (int j = 0; j < 8; j++)
            #pragma unroll
            for (int q = 0; q < 4; q++) acc[i][j][q] = 0.f;

    #pragma unroll
    for (int ks = 0; ks < 8; ks++) {
        unsigned aH[2][4], aL[2][4], bH[8][2], bL[8][2];
        {
            const int r  = wm * 32 + (lane & 15);
            const int kc = ks * 2 + (lane >> 4);
            ldm4(aH[0][0], aH[0][1], aH[0][2], aH[0][3], sb + oAhi + sw_off(r,      kc));
            ldm4(aH[1][0], aH[1][1], aH[1][2], aH[1][3], sb + oAhi + sw_off(r + 16, kc));
            ldm4(aL[0][0], aL[0][1], aL[0][2], aL[0][3], sb + oAlo + sw_off(r,      kc));
            ldm4(aL[1][0], aL[1][1], aL[1][2], aL[1][3], sb + oAlo + sw_off(r + 16, kc));
        }
        {
            const int grp  = lane >> 3;
            const int nloc = (lane & 7) + ((grp >> 1) << 3);
            const int kc   = ks * 2 + (grp & 1);
            #pragma unroll
            for (int j = 0; j < 4; j++) {
                const int n = wn * 64 + j * 16 + nloc;
                ldm4(bH[2*j][0], bH[2*j][1], bH[2*j+1][0], bH[2*j+1][1],
                     sb + oWhi + sw_off(n, kc));
                ldm4(bL[2*j][0], bL[2*j][1], bL[2*j+1][0], bL[2*j+1][1],
                     sb + oWlo + sw_off(n, kc));
            }
        }
        #pragma unroll
        for (int mf = 0; mf < 2; mf++)
            #pragma unroll
            for (int nf = 0; nf < 8; nf++) {
                mma_bf16(acc[mf][nf], aH[mf], bH[nf]);
                mma_bf16(acc[mf][nf], aH[mf], bL[nf]);
                mma_bf16(acc[mf][nf], aL[mf], bH[nf]);
            }
    }
}

__device__ __forceinline__ void epi_f32(
    float acc[2][8][4], const float* sbias, float* C,
    int rowBase, int wm, int wn, int lane, int M)
{
    #pragma unroll
    for (int mf = 0; mf < 2; mf++) {
        const int r0 = rowBase + wm * 32 + mf * 16 + (lane >> 2);
        #pragma unroll
        for (int nf = 0; nf < 8; nf++) {
            const int c  = wn * 64 + nf * 8 + (lane & 3) * 2;
            const float b0 = sbias[c], b1 = sbias[c + 1];
            if (r0 < M)
                *(float2*)(C + (long)r0 * DIM + c) =
                    make_float2(fmaxf(acc[mf][nf][0] + b0, 0.f),
                                fmaxf(acc[mf][nf][1] + b1, 0.f));
            if (r0 + 8 < M)
                *(float2*)(C + (long)(r0 + 8) * DIM + c) =
                    make_float2(fmaxf(acc[mf][nf][2] + b0, 0.f),
                                fmaxf(acc[mf][nf][3] + b1, 0.f));
        }
    }
}

// stage one W pair (hi,lo) from global split tables into smem
__device__ __forceinline__ void stage_w(
    char* sm, unsigned oWhi, unsigned oWlo, int wslot, int tid)
{
    const unsigned short* WH = g_W4[2 * wslot];
    const unsigned short* WL = g_W4[2 * wslot + 1];
    #pragma unroll
    for (int u = 0; u < 8; u++) {
        const int g  = u * 256 + tid;
        const int n  = g >> 4, kc = g & 15;
        const unsigned o = sw_off(n, kc);
        *(uint4*)(sm + oWhi + o) = *(const uint4*)(WH + n * DIM + kc * 8);
        *(uint4*)(sm + oWlo + o) = *(const uint4*)(WL + n * DIM + kc * 8);
    }
}

// ===========================================================================
// Node transforms: 4 weight sets via blockIdx.y (3-term bf16, fp32 out)
// smem: A-hi 32K | A-lo 32K | W-hi 32K | W-lo 32K | bias
// ===========================================================================
#define NSM_AHI  0u
#define NSM_ALO  32768u
#define NSM_WHI  65536u
#define NSM_WLO  98304u
#define NSM_BIAS 131072u
#define NSMEM    131584

struct HSet { int wslot; const float* bias; float* C; };

__global__ void __launch_bounds__(256)
gemm_hmma(const float* __restrict__ A, const int* __restrict__ gidx,
          HSet s0, HSet s1, HSet s2, HSet s3, int M)
{
    const HSet s = (blockIdx.y == 0) ? s0 : (blockIdx.y == 1) ? s1
                 : (blockIdx.y == 2) ? s2 : s3;
    extern __shared__ char sm[];
    const unsigned sb = smem_u32(sm);
    const int tid  = threadIdx.x;
    const int wid  = tid >> 5;
    const int lane = tid & 31;
    const int wm   = wid & 3;
    const int wn   = wid >> 2;
    const int rowBase = blockIdx.x * 128;

    if (tid < 128) ((float*)(sm + NSM_BIAS))[tid] = s.bias[tid];

    #pragma unroll
    for (int u = 0; u < 8; u++) {
        const int g  = u * 256 + tid;
        const int r  = g >> 4, kc = g & 15;
        int R = rowBase + r; if (R >= M) R = M - 1;
        const int src = gidx ? gidx[R] : R;
        const float4 x0 = *(const float4*)(A + (long)src * DIM + kc * 8);
        const float4 x1 = *(const float4*)(A + (long)src * DIM + kc * 8 + 4);
        const float xs[8] = {x0.x, x0.y, x0.z, x0.w, x1.x, x1.y, x1.z, x1.w};
        uint4 H, L;
        split8(xs, H, L);
        const unsigned o = sw_off(r, kc);
        *(uint4*)(sm + NSM_AHI + o) = H;
        *(uint4*)(sm + NSM_ALO + o) = L;
    }
    stage_w(sm, NSM_WHI, NSM_WLO, s.wslot, tid);
    __syncthreads();

    float acc[2][8][4];
    mma3_loop(sb, NSM_AHI, NSM_ALO, NSM_WHI, NSM_WLO, wm, wn, lane, acc);
    epi_f32(acc, (const float*)(sm + NSM_BIAS), s.C, rowBase, wm, wn, lane, M);
}

// ===========================================================================
// Item GEMM: single-term fp16 (output re-rounded to bf16 KV table)
// smem: A 32K | W 32K | bias
// ===========================================================================
#define ISM_A    0u
#define ISM_W    32768u
#define ISM_BIAS 65536u
#define ISMEM    66048

__global__ void __launch_bounds__(256)
gemm_item(const float* __restrict__ A,
          const unsigned short* __restrict__ W0, const unsigned short* __restrict__ W1,
          const float* __restrict__ b0, const float* __restrict__ b1,
          __nv_bfloat16* __restrict__ KV, int M)
{
    const int y = blockIdx.y;
    const unsigned short* Wt = y ? W1 : W0;
    const float* bias = y ? b1 : b0;
    __nv_bfloat16* Cb = KV + (y ? 128 : 0);

    extern __shared__ char sm[];
    const unsigned sb = smem_u32(sm);
    const int tid  = threadIdx.x;
    const int wid  = tid >> 5;
    const int lane = tid & 31;
    const int wm   = wid & 3;
    const int wn   = wid >> 2;
    const int rowBase = blockIdx.x * 128;

    if (tid < 128) ((float*)(sm + ISM_BIAS))[tid] = bias[tid];

    #pragma unroll
    for (int u = 0; u < 8; u++) {
        const int g  = u * 256 + tid;
        const int r  = g >> 4, kc = g & 15;
        int R = rowBase + r; if (R >= M) R = M - 1;
        const float4 x0 = *(const float4*)(A + (long)R * DIM + kc * 8);
        const float4 x1 = *(const float4*)(A + (long)R * DIM + kc * 8 + 4);
        const float xs[8] = {x0.x, x0.y, x0.z, x0.w, x1.x, x1.y, x1.z, x1.w};
        *(uint4*)(sm + ISM_A + sw_off(r, kc)) = pack8f16(xs);
    }
    #pragma unroll
    for (int u = 0; u < 8; u++) {
        const int g  = u * 256 + tid;
        const int n  = g >> 4, kc = g & 15;
        *(uint4*)(sm + ISM_W + sw_off(n, kc)) = *(const uint4*)(Wt + n * DIM + kc * 8);
    }
    __syncthreads();

    float acc[2][8][4];
    #pragma unroll
    for (int i = 0; i < 2; i++)
        #pragma unroll
        for (int j = 0; j < 8; j++)
            #pragma unroll
            for (int q = 0; q < 4; q++) acc[i][j][q] = 0.f;

    #pragma unroll
    for (int ks = 0; ks < 8; ks++) {
        unsigned aH[2][4], bH[8][2];
        {
            const int r  = wm * 32 + (lane & 15);
            const int kc = ks * 2 + (lane >> 4);
            ldm4(aH[0][0], aH[0][1], aH[0][2], aH[0][3], sb + ISM_A + sw_off(r,      kc));
            ldm4(aH[1][0], aH[1][1], aH[1][2], aH[1][3], sb + ISM_A + sw_off(r + 16, kc));
        }
        {
            const int grp  = lane >> 3;
            const int nloc = (lane & 7) + ((grp >> 1) << 3);
            const int kc   = ks * 2 + (grp & 1);
            #pragma unroll
            for (int j = 0; j < 4; j++) {
                const int n = wn * 64 + j * 16 + nloc;
                ldm4(bH[2*j][0], bH[2*j][1], bH[2*j+1][0], bH[2*j+1][1],
                     sb + ISM_W + sw_off(n, kc));
            }
        }
        #pragma unroll
        for (int mf = 0; mf < 2; mf++)
            #pragma unroll
            for (int nf = 0; nf < 8; nf++)
                mma_f16(acc[mf][nf], aH[mf], bH[nf]);
    }

    const float* sbias = (const float*)(sm + ISM_BIAS);
    #pragma unroll
    for (int mf = 0; mf < 2; mf++) {
        const int r0 = rowBase + wm * 32 + mf * 16 + (lane >> 2);
        #pragma unroll
        for (int nf = 0; nf < 8; nf++) {
            const int c  = wn * 64 + nf * 8 + (lane & 3) * 2;
            const float b0v = sbias[c], b1v = sbias[c + 1];
            if (r0 < M) {
                const unsigned v = pack_bf2(fmaxf(acc[mf][nf][0] + b0v, 0.f),
                                            fmaxf(acc[mf][nf][1] + b1v, 0.f));
                *(unsigned*)(Cb + (long)r0 * 256 + c) = v;
            }
            if (r0 + 8 < M) {
                const unsigned v = pack_bf2(fmaxf(acc[mf][nf][2] + b0v, 0.f),
                                            fmaxf(acc[mf][nf][3] + b1v, 0.f));
                *(unsigned*)(Cb + (long)(r0 + 8) * 256 + c) = v;
            }
        }
    }
}

// ===========================================================================
// Fused chain: Agg = relu(Y@wo+bo) (kept in smem) -> K1, V1 (fp32 out)
// smem: A-hi 32K | A-lo 32K | W1 pair 64K | W2 pair 64K | 3 biases
// ===========================================================================
#define CSM_AHI  0u
#define CSM_ALO  32768u
#define CSM_W1H  65536u
#define CSM_W1L  98304u
#define CSM_W2H  131072u
#define CSM_W2L  163840u
#define CSM_BIAS 196608u
#define CSMEM    198144

__global__ void __launch_bounds__(256)
agg_chain(const float* __restrict__ Y,
          const float* __restrict__ bo, const float* __restrict__ bk,
          const float* __restrict__ bv,
          float* __restrict__ K1, float* __restrict__ V1)
{
    extern __shared__ char sm[];
    const unsigned sb = smem_u32(sm);
    const int tid  = threadIdx.x;
    const int wid  = tid >> 5;
    const int lane = tid & 31;
    const int wm   = wid & 3;
    const int wn   = wid >> 2;
    const int rowBase = blockIdx.x * 128;

    if (tid < 128) {
        ((float*)(sm + CSM_BIAS))[tid]       = bo[tid];
        ((float*)(sm + CSM_BIAS + 512))[tid] = bk[tid];
        ((float*)(sm + CSM_BIAS + 1024))[tid]= bv[tid];
    }

    // stage Y split + wo pair + wk pair
    #pragma unroll
    for (int u = 0; u < 8; u++) {
        const int g  = u * 256 + tid;
        const int r  = g >> 4, kc = g & 15;
        const int R = rowBase + r;
        const float4 x0 = *(const float4*)(Y + (long)R * DIM + kc * 8);
        const float4 x1 = *(const float4*)(Y + (long)R * DIM + kc * 8 + 4);
        const float xs[8] = {x0.x, x0.y, x0.z, x0.w, x1.x, x1.y, x1.z, x1.w};
        uint4 H, L;
        split8(xs, H, L);
        const unsigned o = sw_off(r, kc);
        *(uint4*)(sm + CSM_AHI + o) = H;
        *(uint4*)(sm + CSM_ALO + o) = L;
    }
    stage_w(sm, CSM_W1H, CSM_W1L, 3, tid);   // gat_wo
    stage_w(sm, CSM_W2H, CSM_W2L, 5, tid);   // sem_wk
    __syncthreads();

    float acc[2][8][4];

    // phase 1: Agg = relu(Y@wo+bo)
    mma3_loop(sb, CSM_AHI, CSM_ALO, CSM_W1H, CSM_W1L, wm, wn, lane, acc);
    __syncthreads();   // all A/W1 reads done before overwriting

    // write Agg (bf16 hi/lo split) back into the A buffers
    {
        const float* sbo = (const float*)(sm + CSM_BIAS);
        #pragma unroll
        for (int mf = 0; mf < 2; mf++) {
            const int r = wm * 32 + mf * 16 + (lane >> 2);   // row in tile
            #pragma unroll
            for (int nf = 0; nf < 8; nf++) {
                const int c  = wn * 64 + nf * 8 + (lane & 3) * 2;
                const float b0 = sbo[c], b1 = sbo[c + 1];
                const float v0 = fmaxf(acc[mf][nf][0] + b0, 0.f);
                const float v1 = fmaxf(acc[mf][nf][1] + b1, 0.f);
                const float v2 = fmaxf(acc[mf][nf][2] + b0, 0.f);
                const float v3 = fmaxf(acc[mf][nf][3] + b1, 0.f);
                const unsigned off0 = sw_off(r,     c >> 3) + (c & 7) * 2;
                const unsigned off1 = sw_off(r + 8, c >> 3) + (c & 7) * 2;
                // hi
                *(unsigned*)(sm + CSM_AHI + off0) = pack_bf2(v0, v1);
                *(unsigned*)(sm + CSM_AHI + off1) = pack_bf2(v2, v3);
                // lo (residual)
                *(unsigned*)(sm + CSM_ALO + off0) =
                    pack_bf2(v0 - bfhi(pack_bf2(0.f, v0)), v1 - bfhi(pack_bf2(0.f, v1)));
                *(unsigned*)(sm + CSM_ALO + off1) =
                    pack_bf2(v2 - bfhi(pack_bf2(0.f, v2)), v3 - bfhi(pack_bf2(0.f, v3)));
            }
        }
    }
    // reload W1 with sem_wv while A is being finalized
    stage_w(sm, CSM_W1H, CSM_W1L, 6, tid);   // sem_wv
    __syncthreads();

    // phase 2: K1 = relu(Agg@wk+bk)
    mma3_loop(sb, CSM_AHI, CSM_ALO, CSM_W2H, CSM_W2L, wm, wn, lane, acc);
    epi_f32(acc, (const float*)(sm + CSM_BIAS + 512), K1, rowBase, wm, wn, lane, BATCH);

    // phase 3: V1 = relu(Agg@wv+bv)
    mma3_loop(sb, CSM_AHI, CSM_ALO, CSM_W1H, CSM_W1L, wm, wn, lane, acc);
    epi_f32(acc, (const float*)(sm + CSM_BIAS + 1024), V1, rowBase, wm, wn, lane, BATCH);
}

// ===========================================================================
// Fused sem attention + final projection: out = relu(Y2@wo2+bo2),
// Y2 computed per-row during A staging (2-key softmax, half-warp reduce).
// ===========================================================================
__global__ void __launch_bounds__(256)
sem_final(const float* __restrict__ Q2, const float* __restrict__ K0,
          const float* __restrict__ K1, const float* __restrict__ V0,
          const float* __restrict__ V1, const float* __restrict__ bo2,
          float* __restrict__ out)
{
    extern __shared__ char sm[];
    const unsigned sb = smem_u32(sm);
    const int tid  = threadIdx.x;
    const int wid  = tid >> 5;
    const int lane = tid & 31;
    const int wm   = wid & 3;
    const int wn   = wid >> 2;
    const int rowBase = blockIdx.x * 128;

    if (tid < 128) ((float*)(sm + NSM_BIAS))[tid] = bo2[tid];

    const float scale = 0.08838834764831845f;
    #pragma unroll
    for (int u = 0; u < 8; u++) {
        const int g  = u * 256 + tid;
        const int r  = g >> 4, kc = g & 15;
        const long base = (long)(rowBase + r) * DIM + kc * 8;

        const float4 qa = *(const float4*)(Q2 + base);
        const float4 qb = *(const float4*)(Q2 + base + 4);
        const float4 k0a = *(const float4*)(K0 + base);
        const float4 k0b = *(const float4*)(K0 + base + 4);
        const float4 k1a = *(const float4*)(K1 + base);
        const float4 k1b = *(const float4*)(K1 + base + 4);

        float s0 = qa.x*k0a.x + qa.y*k0a.y + qa.z*k0a.z + qa.w*k0a.w
                 + qb.x*k0b.x + qb.y*k0b.y + qb.z*k0b.z + qb.w*k0b.w;
        float s1 = qa.x*k1a.x + qa.y*k1a.y + qa.z*k1a.z + qa.w*k1a.w
                 + qb.x*k1b.x + qb.y*k1b.y + qb.z*k1b.z + qb.w*k1b.w;
        #pragma unroll
        for (int o = 8; o; o >>= 1) {
            s0 += __shfl_xor_sync(0xffffffffu, s0, o);
            s1 += __shfl_xor_sync(0xffffffffu, s1, o);
        }
        s0 *= scale; s1 *= scale;
        const float m  = fmaxf(s0, s1);
        const float e0 = __expf(s0 - m);
        const float e1 = __expf(s1 - m);
        const float inv = 1.0f / (e0 + e1);
        const float p0 = e0 * inv, p1 = e1 * inv;

        const float4 v0a = *(const float4*)(V0 + base);
        const float4 v0b = *(const float4*)(V0 + base + 4);
        const float4 v1a = *(const float4*)(V1 + base);
        const float4 v1b = *(const float4*)(V1 + base + 4);
        const float xs[8] = {
            p0*v0a.x + p1*v1a.x, p0*v0a.y + p1*v1a.y,
            p0*v0a.z + p1*v1a.z, p0*v0a.w + p1*v1a.w,
            p0*v0b.x + p1*v1b.x, p0*v0b.y + p1*v1b.y,
            p0*v0b.z + p1*v1b.z, p0*v0b.w + p1*v1b.w };
        uint4 H, L;
        split8(xs, H, L);
        const unsigned o = sw_off(r, kc);
        *(uint4*)(sm + NSM_AHI + o) = H;
        *(uint4*)(sm + NSM_ALO + o) = L;
    }
    stage_w(sm, NSM_WHI, NSM_WLO, 7, tid);   // sem_wo
    __syncthreads();

    float acc[2][8][4];
    mma3_loop(sb, NSM_AHI, NSM_ALO, NSM_WHI, NSM_WLO, wm, wn, lane, acc);
    epi_f32(acc, (const float*)(sm + NSM_BIAS), out, rowBase, wm, wn, lane, BATCH);
}

// ---------------------------------------------------------------------------
// GAT attention v2 (unchanged from R7): paired-item 16B loads
// ---------------------------------------------------------------------------
__global__ void __launch_bounds__(256)
gat_attn(const float* __restrict__ Q, const int* __restrict__ movies,
         const __nv_bfloat16* __restrict__ KV, float* __restrict__ Y)
{
    const int w    = threadIdx.x >> 5;
    const int lane = threadIdx.x & 31;
    const int half = lane >> 4;
    const int cl   = lane & 15;
    const int b    = blockIdx.x * 8 + w;

    __shared__ int   sidx[8][NHIST];
    __shared__ float sp  [8][NHIST];

    if (lane < NHIST)      sidx[w][lane]      = movies[(b * NHIST + lane) * 2];
    if (lane + 32 < NHIST) sidx[w][lane + 32] = movies[(b * NHIST + lane + 32) * 2];
    __syncwarp();

    const float4 qa = *(const float4*)(Q + (long)b * DIM + cl * 8);
    const float4 qb = *(const float4*)(Q + (long)b * DIM + cl * 8 + 4);

    #pragma unroll
    for (int t0 = 0; t0 < 25; t0 += 5) {
        uint4 kr[5];
        #pragma unroll
        for (int j = 0; j < 5; j++)
            kr[j] = *(const uint4*)(KV + (long)sidx[w][2*(t0+j) + half] * 256 + cl * 8);
        float sc[5];
        #pragma unroll
        for (int j = 0; j < 5; j++) {
            float s;
            s  = qa.x * bflo(kr[j].x) + qa.y * bfhi(kr[j].x);
            s += qa.z * bflo(kr[j].y) + qa.w * bfhi(kr[j].y);
            s += qb.x * bflo(kr[j].z) + qb.y * bfhi(kr[j].z);
            s += qb.z * bflo(kr[j].w) + qb.w * bfhi(kr[j].w);
            sc[j] = s;
        }
        #pragma unroll
        for (int j = 0; j < 5; j++)
            #pragma unroll
            for (int off = 8; off; off >>= 1)
                sc[j] += __shfl_xor_sync(0xffffffffu, sc[j], off);
        if (cl == 0) {
            #pragma unroll
            for (int j = 0; j < 5; j++) sp[w][2*(t0+j) + half] = sc[j];
        }
    }
    __syncwarp();

    const float scale = 0.08838834764831845f;
    float a0 = (lane < NHIST)      ? sp[w][lane]      * scale : -1e30f;
    float a1 = (lane + 32 < NHIST) ? sp[w][lane + 32] * scale : -1e30f;
    float m = fmaxf(a0, a1);
    #pragma unroll
    for (int off = 16; off; off >>= 1)
        m = fmaxf(m, __shfl_xor_sync(0xffffffffu, m, off));
    float e0 = (lane < NHIST)      ? __expf(a0 - m) : 0.f;
    float e1 = (lane + 32 < NHIST) ? __expf(a1 - m) : 0.f;
    float es = e0 + e1;
    #pragma unroll
    for (int off = 16; off; off >>= 1)
        es += __shfl_xor_sync(0xffffffffu, es, off);
    const float inv = 1.0f / es;
    if (lane < NHIST)      sp[w][lane]      = e0 * inv;
    if (lane + 32 < NHIST) sp[w][lane + 32] = e1 * inv;
    __syncwarp();

    float acc[8];
    #pragma unroll
    for (int i = 0; i < 8; i++) acc[i] = 0.f;

    #pragma unroll
    for (int t0 = 0; t0 < 25; t0 += 5) {
        uint4 vr[5];
        float pj[5];
        #pragma unroll
        for (int j = 0; j < 5; j++) {
            vr[j] = *(const uint4*)(KV + (long)sidx[w][2*(t0+j) + half] * 256 + 128 + cl * 8);
            pj[j] = sp[w][2*(t0+j) + half];
        }
        #pragma unroll
        for (int j = 0; j < 5; j++) {
            acc[0] = fmaf(pj[j], bflo(vr[j].x), acc[0]);
            acc[1] = fmaf(pj[j], bfhi(vr[j].x), acc[1]);
            acc[2] = fmaf(pj[j], bflo(vr[j].y), acc[2]);
            acc[3] = fmaf(pj[j], bfhi(vr[j].y), acc[3]);
            acc[4] = fmaf(pj[j], bflo(vr[j].z), acc[4]);
            acc[5] = fmaf(pj[j], bfhi(vr[j].z), acc[5]);
            acc[6] = fmaf(pj[j], bflo(vr[j].w), acc[6]);
            acc[7] = fmaf(pj[j], bfhi(vr[j].w), acc[7]);
        }
    }
    #pragma unroll
    for (int i = 0; i < 8; i++)
        acc[i] += __shfl_xor_sync(0xffffffffu, acc[i], 16);

    if (half == 0) {
        *(float4*)(Y + (long)b * DIM + cl * 8)     = make_float4(acc[0], acc[1], acc[2], acc[3]);
        *(float4*)(Y + (long)b * DIM + cl * 8 + 4) = make_float4(acc[4], acc[5], acc[6], acc[7]);
    }
}

// ---------------------------------------------------------------------------
// Host launcher (6 launches)
// ---------------------------------------------------------------------------
extern "C" void kernel_launch(void* const* d_in, const int* in_sizes, int n_in,
                              void* d_out, int out_size)
{
    const int*   uids       = (const int*)  d_in[0];
    const int*   u_movies   = (const int*)  d_in[2];
    const float* user_table = (const float*)d_in[3];
    const float* item_table = (const float*)d_in[5];
    const float* gat_wq = (const float*)d_in[6],  *gat_bq = (const float*)d_in[7];
    const float* gat_wk = (const float*)d_in[8],  *gat_bk = (const float*)d_in[9];
    const float* gat_wv = (const float*)d_in[10], *gat_bv = (const float*)d_in[11];
    const float* gat_wo = (const float*)d_in[12], *gat_bo = (const float*)d_in[13];
    const float* sem_wq = (const float*)d_in[14], *sem_bq = (const float*)d_in[15];
    const float* sem_wk = (const float*)d_in[16], *sem_bk = (const float*)d_in[17];
    const float* sem_wv = (const float*)d_in[18], *sem_bv = (const float*)d_in[19];
    const float* sem_wo = (const float*)d_in[20], *sem_bo = (const float*)d_in[21];
    float* out = (float*)d_out;

    __nv_bfloat16* KV;
    unsigned short *Wh0, *Wh1;
    float *Qg, *Q2, *K0, *V0, *K1, *V1, *Y;
    cudaGetSymbolAddress((void**)&KV,  g_KV);
    cudaGetSymbolAddress((void**)&Qg,  g_Qg);
    cudaGetSymbolAddress((void**)&Q2,  g_Q2);
    cudaGetSymbolAddress((void**)&K0,  g_K0);
    cudaGetSymbolAddress((void**)&V0,  g_V0);
    cudaGetSymbolAddress((void**)&K1,  g_K1);
    cudaGetSymbolAddress((void**)&V1,  g_V1);
    cudaGetSymbolAddress((void**)&Y,   g_Y);
    {
        void* p;
        cudaGetSymbolAddress(&p, g_Wh);
        Wh0 = (unsigned short*)p;
        Wh1 = Wh0 + DIM * DIM;
    }

    static bool attr_done = false;
    if (!attr_done) {
        cudaFuncSetAttribute(gemm_hmma, cudaFuncAttributeMaxDynamicSharedMemorySize, NSMEM);
        cudaFuncSetAttribute(gemm_item, cudaFuncAttributeMaxDynamicSharedMemorySize, ISMEM);
        cudaFuncSetAttribute(agg_chain, cudaFuncAttributeMaxDynamicSharedMemorySize, CSMEM);
        cudaFuncSetAttribute(sem_final, cudaFuncAttributeMaxDynamicSharedMemorySize, NSMEM);
        attr_done = true;
    }

    const dim3 blk(256);
    const int gItems = (NITEMS + 127) / 128;     // 782
    const int gBatch = BATCH / 128;              // 128

    HSet sQg = { 0, gat_bq, Qg };
    HSet sQ2 = { 4, sem_bq, Q2 };
    HSet sK0 = { 5, sem_bk, K0 };
    HSet sV0 = { 6, sem_bv, V0 };

    // 0: weight transpose + splits
    w_setup<<<64, 256>>>(gat_wq, gat_wk, gat_wv, gat_wo,
                         sem_wq, sem_wk, sem_wv, sem_wo);

    // 1: item K/V -> bf16 KV table (single-term fp16; output re-quantized)
    gemm_item<<<dim3(gItems, 2), blk, ISMEM>>>(item_table, Wh0, Wh1,
                                               gat_bk, gat_bv, KV, NITEMS);

    // 2: node transforms (3-term bf16, fp32 out)
    gemm_hmma<<<dim3(gBatch, 4), blk, NSMEM>>>(user_table, uids,
                                               sQg, sQ2, sK0, sV0, BATCH);

    // 3: GAT attention
    gat_attn<<<BATCH / 8, blk>>>(Qg, u_movies, KV, Y);

    // 4: fused Agg -> K1, V1 (Agg never leaves smem)
    agg_chain<<<gBatch, blk, CSMEM>>>(Y, gat_bo, sem_bk, sem_bv, K1, V1);

    // 5: fused sem attention + final projection into d_out
    sem_final<<<gBatch, blk, NSMEM>>>(Q2, K0, K1, V0, V1, sem_bo, out);
}